// round 3
// baseline (speedup 1.0000x reference)
#include <cuda_runtime.h>
#include <math.h>

#define NN   100000
#define EE   400000
#define GG   2048
#define DIN  128
#define RANK 256

// ---------------- scratch (device globals: no allocations allowed) ----------
__device__ float g_hw  [NN * RANK];   // h @ W
__device__ float g_hact[NN * RANK];   // tanh(agg + b)   (pre-batchnorm)
__device__ int   g_cnt   [NN];
__device__ int   g_cursor[NN];
__device__ int   g_rowptr[NN + 1];
__device__ float g_dinv  [NN];
__device__ int   g_esrc[EE];
__device__ float g_ew  [EE];
__device__ int   g_gptr[GG + 1];
__device__ float g_sum  [RANK];
__device__ float g_sumsq[RANK];
__device__ float g_scale[RANK];
__device__ float g_shift[RANK];
__device__ int   g_part[128];

// ---------------- graph preprocessing (once per call) -----------------------
__global__ void k_init() {
    int i = blockIdx.x * blockDim.x + threadIdx.x;
    if (i < NN) { g_cnt[i] = 0; g_cursor[i] = 0; }
    if (i < RANK) { g_sum[i] = 0.f; g_sumsq[i] = 0.f; }
}

__global__ void k_hist(const int* __restrict__ dst) {
    int e = blockIdx.x * blockDim.x + threadIdx.x;
    if (e < EE) atomicAdd(&g_cnt[dst[e]], 1);
}

__global__ void k_dinv() {
    int v = blockIdx.x * blockDim.x + threadIdx.x;
    if (v == 0) g_rowptr[NN] = EE;
    if (v < NN) g_dinv[v] = rsqrtf((float)(g_cnt[v] + 1));  // +1 self loop
}

// exclusive scan of g_cnt -> g_rowptr  (1024 elems / block, 98 blocks)
__global__ void k_scan1() {
    __shared__ int sm[256];
    int b = blockIdx.x, t = threadIdx.x;
    int base = b * 1024 + t * 4;
    int s = 0;
    #pragma unroll
    for (int j = 0; j < 4; j++) { int i = base + j; if (i < NN) s += g_cnt[i]; }
    sm[t] = s; __syncthreads();
    for (int off = 128; off > 0; off >>= 1) {
        if (t < off) sm[t] += sm[t + off];
        __syncthreads();
    }
    if (t == 0) g_part[b] = sm[0];
}

__global__ void k_scan2() {
    __shared__ int sm[128];
    int t = threadIdx.x;
    int v = (t < 98) ? g_part[t] : 0;
    sm[t] = v; __syncthreads();
    for (int off = 1; off < 128; off <<= 1) {
        int u = (t >= off) ? sm[t - off] : 0;
        __syncthreads();
        sm[t] += u;
        __syncthreads();
    }
    if (t < 98) g_part[t] = sm[t] - v;   // exclusive
}

__global__ void k_scan3() {
    __shared__ int sm[256];
    int b = blockIdx.x, t = threadIdx.x;
    int base = b * 1024 + t * 4;
    int v[4]; int s = 0;
    #pragma unroll
    for (int j = 0; j < 4; j++) { int i = base + j; v[j] = (i < NN) ? g_cnt[i] : 0; s += v[j]; }
    sm[t] = s; __syncthreads();
    for (int off = 1; off < 256; off <<= 1) {
        int u = (t >= off) ? sm[t - off] : 0;
        __syncthreads();
        sm[t] += u;
        __syncthreads();
    }
    int off0 = g_part[b] + (sm[t] - s);  // block offset + thread-exclusive
    int run = 0;
    #pragma unroll
    for (int j = 0; j < 4; j++) {
        int i = base + j;
        if (i < NN) g_rowptr[i] = off0 + run;
        run += v[j];
    }
}

__global__ void k_gptr(const int* __restrict__ batch) {
    int i = blockIdx.x * blockDim.x + threadIdx.x;
    if (i >= NN) return;
    int bi = batch[i];
    if (i == 0) {
        for (int g = 0; g <= bi; g++) g_gptr[g] = 0;
    } else {
        int bp = batch[i - 1];
        for (int g = bp + 1; g <= bi; g++) g_gptr[g] = i;
    }
    if (i == NN - 1) {
        for (int g = bi + 1; g <= GG; g++) g_gptr[g] = NN;
    }
}

__global__ void k_scatter(const int* __restrict__ src, const int* __restrict__ dst) {
    int e = blockIdx.x * blockDim.x + threadIdx.x;
    if (e >= EE) return;
    int s = src[e], d = dst[e];
    int pos = g_rowptr[d] + atomicAdd(&g_cursor[d], 1);
    g_esrc[pos] = s;
    g_ew[pos]   = g_dinv[s] * g_dinv[d];
}

// ---------------- SGEMM: g_hw = A @ W, A = X (layer0) or bn(g_hact) ---------
// BM=BN=128, BK=8, 256 threads, 8x8 per thread.
__global__ void __launch_bounds__(256, 2)
k_gemm(const float* __restrict__ X, const float* __restrict__ W,
       int K, int useNorm) {
    __shared__ float As[8][128];
    __shared__ float Bs[8][128];
    int tid = threadIdx.x;
    int brow = blockIdx.x * 128, bcol = blockIdx.y * 128;
    int tx = tid & 15, ty = tid >> 4;
    int arow = tid >> 1, ak = (tid & 1) * 4;
    int brw = tid >> 5, bc = (tid & 31) * 4;

    float acc[8][8];
    #pragma unroll
    for (int i = 0; i < 8; i++)
        #pragma unroll
        for (int j = 0; j < 8; j++) acc[i][j] = 0.f;

    const float* Aptr = useNorm ? g_hact : X;

    for (int k0 = 0; k0 < K; k0 += 8) {
        int r = brow + arow;
        float4 a = make_float4(0.f, 0.f, 0.f, 0.f);
        if (r < NN) a = *(const float4*)(Aptr + r * K + k0 + ak);
        if (useNorm) {
            int kb = k0 + ak;
            a.x = fmaf(a.x, g_scale[kb + 0], g_shift[kb + 0]);
            a.y = fmaf(a.y, g_scale[kb + 1], g_shift[kb + 1]);
            a.z = fmaf(a.z, g_scale[kb + 2], g_shift[kb + 2]);
            a.w = fmaf(a.w, g_scale[kb + 3], g_shift[kb + 3]);
        }
        As[ak + 0][arow] = a.x;
        As[ak + 1][arow] = a.y;
        As[ak + 2][arow] = a.z;
        As[ak + 3][arow] = a.w;

        *(float4*)&Bs[brw][bc] = *(const float4*)(W + (k0 + brw) * RANK + bcol + bc);
        __syncthreads();

        #pragma unroll
        for (int kk = 0; kk < 8; kk++) {
            float ra[8], rb[8];
            *(float4*)&ra[0] = *(const float4*)&As[kk][ty * 8];
            *(float4*)&ra[4] = *(const float4*)&As[kk][ty * 8 + 4];
            *(float4*)&rb[0] = *(const float4*)&Bs[kk][tx * 8];
            *(float4*)&rb[4] = *(const float4*)&Bs[kk][tx * 8 + 4];
            #pragma unroll
            for (int i = 0; i < 8; i++)
                #pragma unroll
                for (int j = 0; j < 8; j++)
                    acc[i][j] = fmaf(ra[i], rb[j], acc[i][j]);
        }
        __syncthreads();
    }

    #pragma unroll
    for (int i = 0; i < 8; i++) {
        int r = brow + ty * 8 + i;
        if (r < NN) {
            *(float4*)(g_hw + r * RANK + bcol + tx * 8) =
                make_float4(acc[i][0], acc[i][1], acc[i][2], acc[i][3]);
            *(float4*)(g_hw + r * RANK + bcol + tx * 8 + 4) =
                make_float4(acc[i][4], acc[i][5], acc[i][6], acc[i][7]);
        }
    }
}

// ---------------- aggregation + bias + tanh + BN stats ----------------------
#define NPB 32
__global__ void __launch_bounds__(RANK)
k_agg(const float* __restrict__ bias) {
    int c = threadIdx.x;            // column 0..255
    int v0 = blockIdx.x * NPB;
    float bc = bias[c];
    float s = 0.f, s2 = 0.f;
    for (int n = 0; n < NPB; n++) {
        int v = v0 + n;
        if (v >= NN) break;
        int beg = g_rowptr[v], end = g_rowptr[v + 1];
        float di = g_dinv[v];
        float acc = di * di * g_hw[v * RANK + c];   // self loop
        for (int e = beg; e < end; e++) {
            acc = fmaf(g_ew[e], g_hw[g_esrc[e] * RANK + c], acc);
        }
        float h = tanhf(acc + bc);
        g_hact[v * RANK + c] = h;
        s += h; s2 = fmaf(h, h, s2);
    }
    atomicAdd(&g_sum[c], s);
    atomicAdd(&g_sumsq[c], s2);
}

__global__ void k_bnfinal(const float* __restrict__ gamma,
                          const float* __restrict__ beta) {
    int c = threadIdx.x;
    float mu  = g_sum[c]   * (1.0f / NN);
    float var = g_sumsq[c] * (1.0f / NN) - mu * mu;
    float sc  = gamma[c] * rsqrtf(var + 1e-5f);
    g_scale[c] = sc;
    g_shift[c] = beta[c] - mu * sc;
    g_sum[c] = 0.f; g_sumsq[c] = 0.f;      // ready for next layer
}

__global__ void k_pool(float* __restrict__ out) {
    int g = blockIdx.x, c = threadIdx.x;
    int beg = g_gptr[g], end = g_gptr[g + 1];
    float sc = g_scale[c], sh = g_shift[c];
    float m = -INFINITY;
    for (int r = beg; r < end; r++)
        m = fmaxf(m, fmaf(sc, g_hact[r * RANK + c], sh));
    out[g * RANK + c] = (end > beg) ? m : 0.0f;
}

// ---------------- launch ----------------------------------------------------
extern "C" void kernel_launch(void* const* d_in, const int* in_sizes, int n_in,
                              void* d_out, int out_size) {
    const float* x     = (const float*)d_in[0];
    const int*   ei    = (const int*)  d_in[1];   // [2, E] int32 (JAX default x64-off)
    const int*   batch = (const int*)  d_in[2];
    const float* W[3]     = { (const float*)d_in[3],  (const float*)d_in[7],  (const float*)d_in[11] };
    const float* b[3]     = { (const float*)d_in[4],  (const float*)d_in[8],  (const float*)d_in[12] };
    const float* gamma[3] = { (const float*)d_in[5],  (const float*)d_in[9],  (const float*)d_in[13] };
    const float* beta[3]  = { (const float*)d_in[6],  (const float*)d_in[10], (const float*)d_in[14] };
    const int* src = ei;
    const int* dst = ei + EE;
    float* out = (float*)d_out;

    k_init   <<<(NN + 255) / 256, 256>>>();
    k_hist   <<<(EE + 255) / 256, 256>>>(dst);
    k_dinv   <<<(NN + 255) / 256, 256>>>();
    k_scan1  <<<98, 256>>>();
    k_scan2  <<<1, 128>>>();
    k_scan3  <<<98, 256>>>();
    k_gptr   <<<(NN + 255) / 256, 256>>>(batch);
    k_scatter<<<(EE + 255) / 256, 256>>>(src, dst);

    dim3 gemm_grid((NN + 127) / 128, RANK / 128);
    for (int l = 0; l < 3; l++) {
        int K = (l == 0) ? DIN : RANK;
        k_gemm<<<gemm_grid, 256>>>(x, W[l], K, l > 0);
        k_agg <<<(NN + NPB - 1) / NPB, RANK>>>(b[l]);
        k_bnfinal<<<1, RANK>>>(gamma[l], beta[l]);
        k_pool<<<GG, RANK>>>(out + (size_t)l * GG * RANK);
    }
}

// round 4
// speedup vs baseline: 1.2512x; 1.2512x over previous
#include <cuda_runtime.h>
#include <math.h>

#define NN   100000
#define EE   400000
#define GG   2048
#define DIN  128
#define RANK 256

typedef unsigned long long ull;

#define FMA_F32X2(d, a, b, c) \
    asm("fma.rn.f32x2 %0, %1, %2, %3;" : "=l"(d) : "l"(a), "l"(b), "l"(c))
#define BCAST_F32X2(d, f) \
    asm("mov.b64 %0, {%1, %1};" : "=l"(d) : "r"(__float_as_uint(f)))

// ---------------- scratch (device globals: no allocations allowed) ----------
__device__ float g_hw  [NN * RANK];   // h @ W
__device__ float g_hact[NN * RANK];   // tanh(agg + b)   (pre-batchnorm)
__device__ int   g_cnt   [NN];
__device__ int   g_cursor[NN];
__device__ int   g_rowptr[NN + 1];
__device__ float g_dinv  [NN];
__device__ int   g_esrc[EE];
__device__ float g_ew  [EE];
__device__ int   g_gptr[GG + 1];
__device__ float g_sum  [RANK];
__device__ float g_sumsq[RANK];
__device__ float g_scale[RANK];
__device__ float g_shift[RANK];
__device__ int   g_part[128];

// ---------------- graph preprocessing (once per call) -----------------------
__global__ void k_init() {
    int i = blockIdx.x * blockDim.x + threadIdx.x;
    if (i < NN) { g_cnt[i] = 0; g_cursor[i] = 0; }
    if (i < RANK) { g_sum[i] = 0.f; g_sumsq[i] = 0.f; }
}

__global__ void k_hist(const int* __restrict__ dst) {
    int e = blockIdx.x * blockDim.x + threadIdx.x;
    if (e < EE) atomicAdd(&g_cnt[dst[e]], 1);
}

__global__ void k_dinv() {
    int v = blockIdx.x * blockDim.x + threadIdx.x;
    if (v == 0) g_rowptr[NN] = EE;
    if (v < NN) g_dinv[v] = rsqrtf((float)(g_cnt[v] + 1));  // +1 self loop
}

// exclusive scan of g_cnt -> g_rowptr  (1024 elems / block, 98 blocks)
__global__ void k_scan1() {
    __shared__ int sm[256];
    int b = blockIdx.x, t = threadIdx.x;
    int base = b * 1024 + t * 4;
    int s = 0;
    #pragma unroll
    for (int j = 0; j < 4; j++) { int i = base + j; if (i < NN) s += g_cnt[i]; }
    sm[t] = s; __syncthreads();
    for (int off = 128; off > 0; off >>= 1) {
        if (t < off) sm[t] += sm[t + off];
        __syncthreads();
    }
    if (t == 0) g_part[b] = sm[0];
}

__global__ void k_scan2() {
    __shared__ int sm[128];
    int t = threadIdx.x;
    int v = (t < 98) ? g_part[t] : 0;
    sm[t] = v; __syncthreads();
    for (int off = 1; off < 128; off <<= 1) {
        int u = (t >= off) ? sm[t - off] : 0;
        __syncthreads();
        sm[t] += u;
        __syncthreads();
    }
    if (t < 98) g_part[t] = sm[t] - v;   // exclusive
}

__global__ void k_scan3() {
    __shared__ int sm[256];
    int b = blockIdx.x, t = threadIdx.x;
    int base = b * 1024 + t * 4;
    int v[4]; int s = 0;
    #pragma unroll
    for (int j = 0; j < 4; j++) { int i = base + j; v[j] = (i < NN) ? g_cnt[i] : 0; s += v[j]; }
    sm[t] = s; __syncthreads();
    for (int off = 1; off < 256; off <<= 1) {
        int u = (t >= off) ? sm[t - off] : 0;
        __syncthreads();
        sm[t] += u;
        __syncthreads();
    }
    int off0 = g_part[b] + (sm[t] - s);  // block offset + thread-exclusive
    int run = 0;
    #pragma unroll
    for (int j = 0; j < 4; j++) {
        int i = base + j;
        if (i < NN) g_rowptr[i] = off0 + run;
        run += v[j];
    }
}

__global__ void k_gptr(const int* __restrict__ batch) {
    int i = blockIdx.x * blockDim.x + threadIdx.x;
    if (i >= NN) return;
    int bi = batch[i];
    if (i == 0) {
        for (int g = 0; g <= bi; g++) g_gptr[g] = 0;
    } else {
        int bp = batch[i - 1];
        for (int g = bp + 1; g <= bi; g++) g_gptr[g] = i;
    }
    if (i == NN - 1) {
        for (int g = bi + 1; g <= GG; g++) g_gptr[g] = NN;
    }
}

__global__ void k_scatter(const int* __restrict__ src, const int* __restrict__ dst) {
    int e = blockIdx.x * blockDim.x + threadIdx.x;
    if (e >= EE) return;
    int s = src[e], d = dst[e];
    int pos = g_rowptr[d] + atomicAdd(&g_cursor[d], 1);
    g_esrc[pos] = s;
    g_ew[pos]   = g_dinv[s] * g_dinv[d];
}

// ---------------- SGEMM: g_hw = A @ W, A = X (layer0) or bn(g_hact) ---------
// BM=BN=128, BK=8, 256 threads, 8x8 per thread via packed fma.rn.f32x2
// (accumulators held as 8x4 f32x2 pairs over the column dimension).
__global__ void __launch_bounds__(256, 2)
k_gemm(const float* __restrict__ X, const float* __restrict__ W,
       int K, int useNorm) {
    __shared__ __align__(16) float As[8][128];
    __shared__ __align__(16) float Bs[8][128];
    int tid = threadIdx.x;
    int brow = blockIdx.x * 128, bcol = blockIdx.y * 128;
    int tx = tid & 15, ty = tid >> 4;
    int arow = tid >> 1, ak = (tid & 1) * 4;
    int brw = tid >> 5, bc = (tid & 31) * 4;

    ull accp[8][4];
    #pragma unroll
    for (int i = 0; i < 8; i++)
        #pragma unroll
        for (int j = 0; j < 4; j++) accp[i][j] = 0ull;   // == {0.f, 0.f}

    const float* Aptr = useNorm ? g_hact : X;

    for (int k0 = 0; k0 < K; k0 += 8) {
        int r = brow + arow;
        float4 a = make_float4(0.f, 0.f, 0.f, 0.f);
        if (r < NN) a = *(const float4*)(Aptr + (size_t)r * K + k0 + ak);
        if (useNorm) {
            int kb = k0 + ak;
            a.x = fmaf(a.x, g_scale[kb + 0], g_shift[kb + 0]);
            a.y = fmaf(a.y, g_scale[kb + 1], g_shift[kb + 1]);
            a.z = fmaf(a.z, g_scale[kb + 2], g_shift[kb + 2]);
            a.w = fmaf(a.w, g_scale[kb + 3], g_shift[kb + 3]);
        }
        As[ak + 0][arow] = a.x;
        As[ak + 1][arow] = a.y;
        As[ak + 2][arow] = a.z;
        As[ak + 3][arow] = a.w;

        *(float4*)&Bs[brw][bc] = *(const float4*)(W + (size_t)(k0 + brw) * RANK + bcol + bc);
        __syncthreads();

        #pragma unroll
        for (int kk = 0; kk < 8; kk++) {
            float ra[8];
            *(float4*)&ra[0] = *(const float4*)&As[kk][ty * 8];
            *(float4*)&ra[4] = *(const float4*)&As[kk][ty * 8 + 4];
            ull ra2[8];
            #pragma unroll
            for (int i = 0; i < 8; i++) BCAST_F32X2(ra2[i], ra[i]);

            ull rb2[4];
            ulonglong2 t0 = *(const ulonglong2*)&Bs[kk][tx * 8];
            ulonglong2 t1 = *(const ulonglong2*)&Bs[kk][tx * 8 + 4];
            rb2[0] = t0.x; rb2[1] = t0.y; rb2[2] = t1.x; rb2[3] = t1.y;

            #pragma unroll
            for (int i = 0; i < 8; i++)
                #pragma unroll
                for (int j = 0; j < 4; j++)
                    FMA_F32X2(accp[i][j], ra2[i], rb2[j], accp[i][j]);
        }
        __syncthreads();
    }

    #pragma unroll
    for (int i = 0; i < 8; i++) {
        int r = brow + ty * 8 + i;
        if (r < NN) {
            float v[8];
            #pragma unroll
            for (int j = 0; j < 4; j++) {
                float2 p = *(float2*)&accp[i][j];
                v[2 * j] = p.x; v[2 * j + 1] = p.y;
            }
            *(float4*)(g_hw + (size_t)r * RANK + bcol + tx * 8) =
                make_float4(v[0], v[1], v[2], v[3]);
            *(float4*)(g_hw + (size_t)r * RANK + bcol + tx * 8 + 4) =
                make_float4(v[4], v[5], v[6], v[7]);
        }
    }
}

// ---------------- aggregation + bias + tanh + BN stats ----------------------
// 256 threads: 64 column-groups (float4) x 4 node-subsets.
#define NPB 32
__global__ void __launch_bounds__(256)
k_agg(const float* __restrict__ bias) {
    __shared__ float ssum[RANK], ssq[RANK];
    int tid = threadIdx.x;
    int cg  = (tid & 63) * 4;      // column group base
    int sub = tid >> 6;            // node subset 0..3
    if (tid < RANK) { ssum[tid] = 0.f; ssq[tid] = 0.f; }
    __syncthreads();

    float4 bc = *(const float4*)(bias + cg);
    float s0 = 0.f, s1 = 0.f, s2v = 0.f, s3 = 0.f;
    float q0 = 0.f, q1 = 0.f, q2 = 0.f, q3 = 0.f;
    int v0 = blockIdx.x * NPB;

    for (int n = sub; n < NPB; n += 4) {
        int v = v0 + n;
        if (v >= NN) break;
        int beg = g_rowptr[v], end = g_rowptr[v + 1];
        float di = g_dinv[v];
        float w0 = di * di;
        float4 hv = *(const float4*)(g_hw + (size_t)v * RANK + cg);
        float4 acc = make_float4(w0 * hv.x, w0 * hv.y, w0 * hv.z, w0 * hv.w);
        for (int e = beg; e < end; e++) {
            float w = g_ew[e];
            const float4 hs = *(const float4*)(g_hw + (size_t)g_esrc[e] * RANK + cg);
            acc.x = fmaf(w, hs.x, acc.x);
            acc.y = fmaf(w, hs.y, acc.y);
            acc.z = fmaf(w, hs.z, acc.z);
            acc.w = fmaf(w, hs.w, acc.w);
        }
        float4 h;
        h.x = tanhf(acc.x + bc.x);
        h.y = tanhf(acc.y + bc.y);
        h.z = tanhf(acc.z + bc.z);
        h.w = tanhf(acc.w + bc.w);
        *(float4*)(g_hact + (size_t)v * RANK + cg) = h;
        s0 += h.x; s1 += h.y; s2v += h.z; s3 += h.w;
        q0 = fmaf(h.x, h.x, q0); q1 = fmaf(h.y, h.y, q1);
        q2 = fmaf(h.z, h.z, q2); q3 = fmaf(h.w, h.w, q3);
    }

    atomicAdd(&ssum[cg + 0], s0);  atomicAdd(&ssq[cg + 0], q0);
    atomicAdd(&ssum[cg + 1], s1);  atomicAdd(&ssq[cg + 1], q1);
    atomicAdd(&ssum[cg + 2], s2v); atomicAdd(&ssq[cg + 2], q2);
    atomicAdd(&ssum[cg + 3], s3);  atomicAdd(&ssq[cg + 3], q3);
    __syncthreads();
    if (tid < RANK) {
        atomicAdd(&g_sum[tid],   ssum[tid]);
        atomicAdd(&g_sumsq[tid], ssq[tid]);
    }
}

__global__ void k_bnfinal(const float* __restrict__ gamma,
                          const float* __restrict__ beta) {
    int c = threadIdx.x;
    float mu  = g_sum[c]   * (1.0f / NN);
    float var = g_sumsq[c] * (1.0f / NN) - mu * mu;
    float sc  = gamma[c] * rsqrtf(var + 1e-5f);
    g_scale[c] = sc;
    g_shift[c] = beta[c] - mu * sc;
    g_sum[c] = 0.f; g_sumsq[c] = 0.f;      // ready for next layer
}

__global__ void k_pool(float* __restrict__ out) {
    int g = blockIdx.x, c = threadIdx.x;
    int beg = g_gptr[g], end = g_gptr[g + 1];
    float sc = g_scale[c], sh = g_shift[c];
    float m = -INFINITY;
    for (int r = beg; r < end; r++)
        m = fmaxf(m, fmaf(sc, g_hact[(size_t)r * RANK + c], sh));
    out[(size_t)g * RANK + c] = (end > beg) ? m : 0.0f;
}

// ---------------- launch ----------------------------------------------------
extern "C" void kernel_launch(void* const* d_in, const int* in_sizes, int n_in,
                              void* d_out, int out_size) {
    const float* x     = (const float*)d_in[0];
    const int*   ei    = (const int*)  d_in[1];   // [2, E] int32
    const int*   batch = (const int*)  d_in[2];
    const float* W[3]     = { (const float*)d_in[3],  (const float*)d_in[7],  (const float*)d_in[11] };
    const float* b[3]     = { (const float*)d_in[4],  (const float*)d_in[8],  (const float*)d_in[12] };
    const float* gamma[3] = { (const float*)d_in[5],  (const float*)d_in[9],  (const float*)d_in[13] };
    const float* beta[3]  = { (const float*)d_in[6],  (const float*)d_in[10], (const float*)d_in[14] };
    const int* src = ei;
    const int* dst = ei + EE;
    float* out = (float*)d_out;

    k_init   <<<(NN + 255) / 256, 256>>>();
    k_hist   <<<(EE + 255) / 256, 256>>>(dst);
    k_dinv   <<<(NN + 255) / 256, 256>>>();
    k_scan1  <<<98, 256>>>();
    k_scan2  <<<1, 128>>>();
    k_scan3  <<<98, 256>>>();
    k_gptr   <<<(NN + 255) / 256, 256>>>(batch);
    k_scatter<<<(EE + 255) / 256, 256>>>(src, dst);

    dim3 gemm_grid((NN + 127) / 128, RANK / 128);
    for (int l = 0; l < 3; l++) {
        int K = (l == 0) ? DIN : RANK;
        k_gemm<<<gemm_grid, 256>>>(x, W[l], K, l > 0);
        k_agg <<<(NN + NPB - 1) / NPB, RANK>>>(b[l]);
        k_bnfinal<<<1, RANK>>>(gamma[l], beta[l]);
        k_pool<<<GG, RANK>>>(out + (size_t)l * GG * RANK);
    }
}

// round 6
// speedup vs baseline: 1.7165x; 1.3719x over previous
#include <cuda_runtime.h>
#include <cuda_bf16.h>
#include <math.h>
#include <stdint.h>

#define NN   100000
#define NPAD 100096          // 782 * 128
#define EE   400000
#define GG   2048
#define DIN  128
#define RANK 256

// ---------------- scratch (device globals: no allocations allowed) ----------
__device__ float g_hw  [NN * RANK];   // h @ W   (fp32, MMA epilogue output)
__device__ float g_hact[NN * RANK];   // tanh(agg + b)   (pre-batchnorm)
__device__ __nv_bfloat16 g_ahi[NPAD * RANK];  // A split hi (lda = DIN or RANK)
__device__ __nv_bfloat16 g_alo[NPAD * RANK];  // A split lo
__device__ __nv_bfloat16 g_whi[RANK * RANK];  // W^T split hi  [n][k] K-major
__device__ __nv_bfloat16 g_wlo[RANK * RANK];  // W^T split lo
__device__ int   g_cnt   [NN];
__device__ int   g_cursor[NN];
__device__ int   g_rowptr[NN + 1];
__device__ float g_dinv  [NN];
__device__ int   g_esrc[EE];
__device__ float g_ew  [EE];
__device__ int   g_gptr[GG + 1];
__device__ float g_sum  [RANK];
__device__ float g_sumsq[RANK];
__device__ float g_scale[RANK];
__device__ float g_shift[RANK];
__device__ int   g_part[128];

// ---------------- graph preprocessing (once per call) -----------------------
__global__ void k_init() {
    int i = blockIdx.x * blockDim.x + threadIdx.x;
    if (i < NN) { g_cnt[i] = 0; g_cursor[i] = 0; }
    if (i < RANK) { g_sum[i] = 0.f; g_sumsq[i] = 0.f; }
}

__global__ void k_hist(const int* __restrict__ dst) {
    int e = blockIdx.x * blockDim.x + threadIdx.x;
    if (e < EE) atomicAdd(&g_cnt[dst[e]], 1);
}

__global__ void k_dinv() {
    int v = blockIdx.x * blockDim.x + threadIdx.x;
    if (v == 0) g_rowptr[NN] = EE;
    if (v < NN) g_dinv[v] = rsqrtf((float)(g_cnt[v] + 1));  // +1 self loop
}

__global__ void k_scan1() {
    __shared__ int sm[256];
    int b = blockIdx.x, t = threadIdx.x;
    int base = b * 1024 + t * 4;
    int s = 0;
    #pragma unroll
    for (int j = 0; j < 4; j++) { int i = base + j; if (i < NN) s += g_cnt[i]; }
    sm[t] = s; __syncthreads();
    for (int off = 128; off > 0; off >>= 1) {
        if (t < off) sm[t] += sm[t + off];
        __syncthreads();
    }
    if (t == 0) g_part[b] = sm[0];
}

__global__ void k_scan2() {
    __shared__ int sm[128];
    int t = threadIdx.x;
    int v = (t < 98) ? g_part[t] : 0;
    sm[t] = v; __syncthreads();
    for (int off = 1; off < 128; off <<= 1) {
        int u = (t >= off) ? sm[t - off] : 0;
        __syncthreads();
        sm[t] += u;
        __syncthreads();
    }
    if (t < 98) g_part[t] = sm[t] - v;   // exclusive
}

__global__ void k_scan3() {
    __shared__ int sm[256];
    int b = blockIdx.x, t = threadIdx.x;
    int base = b * 1024 + t * 4;
    int v[4]; int s = 0;
    #pragma unroll
    for (int j = 0; j < 4; j++) { int i = base + j; v[j] = (i < NN) ? g_cnt[i] : 0; s += v[j]; }
    sm[t] = s; __syncthreads();
    for (int off = 1; off < 256; off <<= 1) {
        int u = (t >= off) ? sm[t - off] : 0;
        __syncthreads();
        sm[t] += u;
        __syncthreads();
    }
    int off0 = g_part[b] + (sm[t] - s);
    int run = 0;
    #pragma unroll
    for (int j = 0; j < 4; j++) {
        int i = base + j;
        if (i < NN) g_rowptr[i] = off0 + run;
        run += v[j];
    }
}

__global__ void k_gptr(const int* __restrict__ batch) {
    int i = blockIdx.x * blockDim.x + threadIdx.x;
    if (i >= NN) return;
    int bi = batch[i];
    if (i == 0) {
        for (int g = 0; g <= bi; g++) g_gptr[g] = 0;
    } else {
        int bp = batch[i - 1];
        for (int g = bp + 1; g <= bi; g++) g_gptr[g] = i;
    }
    if (i == NN - 1) {
        for (int g = bi + 1; g <= GG; g++) g_gptr[g] = NN;
    }
}

__global__ void k_scatter(const int* __restrict__ src, const int* __restrict__ dst) {
    int e = blockIdx.x * blockDim.x + threadIdx.x;
    if (e >= EE) return;
    int s = src[e], d = dst[e];
    int pos = g_rowptr[d] + atomicAdd(&g_cursor[d], 1);
    g_esrc[pos] = s;
    g_ew[pos]   = g_dinv[s] * g_dinv[d];
}

// ---------------- bf16 split conversions -------------------------------------
__device__ __forceinline__ void bf16_split(float v, __nv_bfloat16& hi, __nv_bfloat16& lo) {
    hi = __float2bfloat16(v);
    lo = __float2bfloat16(v - __bfloat162float(hi));
}

// W[K x RANK] row-major -> W^T [RANK x K] K-major, split hi/lo
__global__ void k_convW(const float* __restrict__ W, int K) {
    int i = blockIdx.x * blockDim.x + threadIdx.x;   // i over RANK*K
    if (i >= RANK * K) return;
    int n = i / K, k = i - n * K;
    float v = W[(size_t)k * RANK + n];
    __nv_bfloat16 hi, lo; bf16_split(v, hi, lo);
    g_whi[i] = hi; g_wlo[i] = lo;
}

// x [NN x DIN] fp32 -> g_ahi/g_alo packed (lda = DIN)
__global__ void k_convX(const float* __restrict__ x) {
    int i4 = blockIdx.x * blockDim.x + threadIdx.x;  // float4 index
    if (i4 >= NN * DIN / 4) return;
    float4 v = ((const float4*)x)[i4];
    __nv_bfloat16 h0,l0,h1,l1,h2,l2,h3,l3;
    bf16_split(v.x,h0,l0); bf16_split(v.y,h1,l1);
    bf16_split(v.z,h2,l2); bf16_split(v.w,h3,l3);
    __nv_bfloat16* dh = g_ahi + (size_t)i4 * 4;
    __nv_bfloat16* dl = g_alo + (size_t)i4 * 4;
    dh[0]=h0; dh[1]=h1; dh[2]=h2; dh[3]=h3;
    dl[0]=l0; dl[1]=l1; dl[2]=l2; dl[3]=l3;
}

// bn(g_hact) -> g_ahi/g_alo packed (lda = RANK)
__global__ void k_bnconv() {
    int i4 = blockIdx.x * blockDim.x + threadIdx.x;
    if (i4 >= NN * RANK / 4) return;
    int c0 = (i4 & 63) * 4;
    float4 h = ((const float4*)g_hact)[i4];
    float4 sc = *(const float4*)(g_scale + c0);
    float4 sh = *(const float4*)(g_shift + c0);
    float4 v;
    v.x = fmaf(h.x, sc.x, sh.x); v.y = fmaf(h.y, sc.y, sh.y);
    v.z = fmaf(h.z, sc.z, sh.z); v.w = fmaf(h.w, sc.w, sh.w);
    __nv_bfloat16 h0,l0,h1,l1,h2,l2,h3,l3;
    bf16_split(v.x,h0,l0); bf16_split(v.y,h1,l1);
    bf16_split(v.z,h2,l2); bf16_split(v.w,h3,l3);
    __nv_bfloat16* dh = g_ahi + (size_t)i4 * 4;
    __nv_bfloat16* dl = g_alo + (size_t)i4 * 4;
    dh[0]=h0; dh[1]=h1; dh[2]=h2; dh[3]=h3;
    dl[0]=l0; dl[1]=l1; dl[2]=l2; dl[3]=l3;
}

// ---------------- mma.sync bf16-split GEMM -----------------------------------
// g_hw[128-row tile][256] = Ahi@Whi^T + Ahi@Wlo^T + Alo@Whi^T  (fp32 accum)
// CTA: 128x256, 512 threads (16 warps 2x8), warp tile 64x32, K chunk 64.
#define ASTRIDE 72   // padded bf16 row stride (144B) -> conflict-free LDS
#define SA_ELEM (128 * ASTRIDE)
#define SB_ELEM (256 * ASTRIDE)
#define GEMM_SMEM ((2 * SA_ELEM + 2 * SB_ELEM) * 2)   // 110592 bytes

#define MMA16816(C, A, B) \
    asm volatile("mma.sync.aligned.m16n8k16.row.col.f32.bf16.bf16.f32 " \
        "{%0,%1,%2,%3}, {%4,%5,%6,%7}, {%8,%9}, {%0,%1,%2,%3};" \
        : "+f"((C)[0]), "+f"((C)[1]), "+f"((C)[2]), "+f"((C)[3]) \
        : "r"((A)[0]), "r"((A)[1]), "r"((A)[2]), "r"((A)[3]), \
          "r"((B)[0]), "r"((B)[1]))

__global__ void __launch_bounds__(512, 1)
k_gemm_mma(int K) {
    extern __shared__ __align__(16) char smem[];
    __nv_bfloat16* sAh = (__nv_bfloat16*)smem;         // [128][72]
    __nv_bfloat16* sAl = sAh + SA_ELEM;
    __nv_bfloat16* sBh = sAl + SA_ELEM;                // [256][72]
    __nv_bfloat16* sBl = sBh + SB_ELEM;

    int tid = threadIdx.x;
    int wid = tid >> 5, lid = tid & 31;
    int m0  = blockIdx.x * 128;
    int wm  = (wid & 1) * 64;     // warp M offset within CTA tile
    int wn  = (wid >> 1) * 32;    // warp N offset
    int lr  = lid >> 2;           // 0..7
    int lc  = lid & 3;            // 0..3 (k-pair / n-pair index)

    float c[4][4][4];
    #pragma unroll
    for (int i = 0; i < 4; i++)
        #pragma unroll
        for (int j = 0; j < 4; j++)
            #pragma unroll
            for (int q = 0; q < 4; q++) c[i][j][q] = 0.f;

    for (int kc = 0; kc < K; kc += 64) {
        // A chunk: 128 rows x 64 bf16 (hi+lo) -> 1024 uint4 each, 2/thread
        #pragma unroll
        for (int j = 0; j < 2; j++) {
            int i = tid * 2 + j;
            int r = i >> 3, kg = i & 7;
            size_t go = (size_t)(m0 + r) * K + kc;
            *(uint4*)(sAh + r * ASTRIDE + kg * 8) = *((const uint4*)(g_ahi + go) + kg);
            *(uint4*)(sAl + r * ASTRIDE + kg * 8) = *((const uint4*)(g_alo + go) + kg);
        }
        // B chunk: 256 n-rows x 64 bf16 (hi+lo) -> 2048 uint4 each, 4/thread
        #pragma unroll
        for (int j = 0; j < 4; j++) {
            int i = tid * 4 + j;
            int n = i >> 3, kg = i & 7;
            size_t go = (size_t)n * K + kc;
            *(uint4*)(sBh + n * ASTRIDE + kg * 8) = *((const uint4*)(g_whi + go) + kg);
            *(uint4*)(sBl + n * ASTRIDE + kg * 8) = *((const uint4*)(g_wlo + go) + kg);
        }
        __syncthreads();

        #pragma unroll
        for (int ks = 0; ks < 4; ks++) {
            int koff = ks * 16 + lc * 2;
            uint32_t bh[4][2], bl[4][2];
            #pragma unroll
            for (int fn = 0; fn < 4; fn++) {
                int n = wn + fn * 8 + lr;
                bh[fn][0] = *(const uint32_t*)(sBh + n * ASTRIDE + koff);
                bh[fn][1] = *(const uint32_t*)(sBh + n * ASTRIDE + koff + 8);
                bl[fn][0] = *(const uint32_t*)(sBl + n * ASTRIDE + koff);
                bl[fn][1] = *(const uint32_t*)(sBl + n * ASTRIDE + koff + 8);
            }
            #pragma unroll
            for (int fm = 0; fm < 4; fm++) {
                int m = wm + fm * 16 + lr;
                uint32_t ah[4], al[4];
                ah[0] = *(const uint32_t*)(sAh + m * ASTRIDE + koff);
                ah[1] = *(const uint32_t*)(sAh + (m + 8) * ASTRIDE + koff);
                ah[2] = *(const uint32_t*)(sAh + m * ASTRIDE + koff + 8);
                ah[3] = *(const uint32_t*)(sAh + (m + 8) * ASTRIDE + koff + 8);
                al[0] = *(const uint32_t*)(sAl + m * ASTRIDE + koff);
                al[1] = *(const uint32_t*)(sAl + (m + 8) * ASTRIDE + koff);
                al[2] = *(const uint32_t*)(sAl + m * ASTRIDE + koff + 8);
                al[3] = *(const uint32_t*)(sAl + (m + 8) * ASTRIDE + koff + 8);
                #pragma unroll
                for (int fn = 0; fn < 4; fn++) {
                    MMA16816(c[fm][fn], ah, bh[fn]);
                    MMA16816(c[fm][fn], ah, bl[fn]);
                    MMA16816(c[fm][fn], al, bh[fn]);
                }
            }
        }
        __syncthreads();
    }

    // epilogue: fragment -> g_hw
    #pragma unroll
    for (int fm = 0; fm < 4; fm++) {
        int r0 = m0 + wm + fm * 16 + lr;
        int r1 = r0 + 8;
        #pragma unroll
        for (int fn = 0; fn < 4; fn++) {
            int col = wn + fn * 8 + lc * 2;
            if (r0 < NN)
                *(float2*)(g_hw + (size_t)r0 * RANK + col) =
                    make_float2(c[fm][fn][0], c[fm][fn][1]);
            if (r1 < NN)
                *(float2*)(g_hw + (size_t)r1 * RANK + col) =
                    make_float2(c[fm][fn][2], c[fm][fn][3]);
        }
    }
}

// ---------------- aggregation + bias + tanh + BN stats ----------------------
#define NPB 32
__global__ void __launch_bounds__(256)
k_agg(const float* __restrict__ bias) {
    __shared__ float ssum[RANK], ssq[RANK];
    int tid = threadIdx.x;
    int cg  = (tid & 63) * 4;
    int sub = tid >> 6;
    if (tid < RANK) { ssum[tid] = 0.f; ssq[tid] = 0.f; }
    __syncthreads();

    float4 bc = *(const float4*)(bias + cg);
    float s0 = 0.f, s1 = 0.f, s2v = 0.f, s3 = 0.f;
    float q0 = 0.f, q1 = 0.f, q2 = 0.f, q3 = 0.f;
    int v0 = blockIdx.x * NPB;

    for (int n = sub; n < NPB; n += 4) {
        int v = v0 + n;
        if (v >= NN) break;
        int beg = g_rowptr[v], end = g_rowptr[v + 1];
        float di = g_dinv[v];
        float w0 = di * di;
        float4 hv = *(const float4*)(g_hw + (size_t)v * RANK + cg);
        float4 acc = make_float4(w0 * hv.x, w0 * hv.y, w0 * hv.z, w0 * hv.w);
        for (int e = beg; e < end; e++) {
            float w = g_ew[e];
            const float4 hs = *(const float4*)(g_hw + (size_t)g_esrc[e] * RANK + cg);
            acc.x = fmaf(w, hs.x, acc.x);
            acc.y = fmaf(w, hs.y, acc.y);
            acc.z = fmaf(w, hs.z, acc.z);
            acc.w = fmaf(w, hs.w, acc.w);
        }
        float4 h;
        h.x = tanhf(acc.x + bc.x);
        h.y = tanhf(acc.y + bc.y);
        h.z = tanhf(acc.z + bc.z);
        h.w = tanhf(acc.w + bc.w);
        *(float4*)(g_hact + (size_t)v * RANK + cg) = h;
        s0 += h.x; s1 += h.y; s2v += h.z; s3 += h.w;
        q0 = fmaf(h.x, h.x, q0); q1 = fmaf(h.y, h.y, q1);
        q2 = fmaf(h.z, h.z, q2); q3 = fmaf(h.w, h.w, q3);
    }

    atomicAdd(&ssum[cg + 0], s0);  atomicAdd(&ssq[cg + 0], q0);
    atomicAdd(&ssum[cg + 1], s1);  atomicAdd(&ssq[cg + 1], q1);
    atomicAdd(&ssum[cg + 2], s2v); atomicAdd(&ssq[cg + 2], q2);
    atomicAdd(&ssum[cg + 3], s3);  atomicAdd(&ssq[cg + 3], q3);
    __syncthreads();
    if (tid < RANK) {
        atomicAdd(&g_sum[tid],   ssum[tid]);
        atomicAdd(&g_sumsq[tid], ssq[tid]);
    }
}

__global__ void k_bnfinal(const float* __restrict__ gamma,
                          const float* __restrict__ beta) {
    int c = threadIdx.x;
    float mu  = g_sum[c]   * (1.0f / NN);
    float var = g_sumsq[c] * (1.0f / NN) - mu * mu;
    float sc  = gamma[c] * rsqrtf(var + 1e-5f);
    g_scale[c] = sc;
    g_shift[c] = beta[c] - mu * sc;
    g_sum[c] = 0.f; g_sumsq[c] = 0.f;
}

__global__ void k_pool(float* __restrict__ out) {
    int g = blockIdx.x, c = threadIdx.x;
    int beg = g_gptr[g], end = g_gptr[g + 1];
    float sc = g_scale[c], sh = g_shift[c];
    float m = -INFINITY;
    for (int r = beg; r < end; r++)
        m = fmaxf(m, fmaf(sc, g_hact[(size_t)r * RANK + c], sh));
    out[(size_t)g * RANK + c] = (end > beg) ? m : 0.0f;
}

// ---------------- launch ----------------------------------------------------
extern "C" void kernel_launch(void* const* d_in, const int* in_sizes, int n_in,
                              void* d_out, int out_size) {
    const float* x     = (const float*)d_in[0];
    const int*   ei    = (const int*)  d_in[1];   // [2, E] int32
    const int*   batch = (const int*)  d_in[2];
    const float* W[3]     = { (const float*)d_in[3],  (const float*)d_in[7],  (const float*)d_in[11] };
    const float* b[3]     = { (const float*)d_in[4],  (const float*)d_in[8],  (const float*)d_in[12] };
    const float* gamma[3] = { (const float*)d_in[5],  (const float*)d_in[9],  (const float*)d_in[13] };
    const float* beta[3]  = { (const float*)d_in[6],  (const float*)d_in[10], (const float*)d_in[14] };
    const int* src = ei;
    const int* dst = ei + EE;
    float* out = (float*)d_out;

    cudaFuncSetAttribute(k_gemm_mma, cudaFuncAttributeMaxDynamicSharedMemorySize, GEMM_SMEM);

    k_init   <<<(NN + 255) / 256, 256>>>();
    k_hist   <<<(EE + 255) / 256, 256>>>(dst);
    k_dinv   <<<(NN + 255) / 256, 256>>>();
    k_scan1  <<<98, 256>>>();
    k_scan2  <<<1, 128>>>();
    k_scan3  <<<98, 256>>>();
    k_gptr   <<<(NN + 255) / 256, 256>>>(batch);
    k_scatter<<<(EE + 255) / 256, 256>>>(src, dst);
    k_convX  <<<(NN * DIN / 4 + 255) / 256, 256>>>(x);

    int mtiles = (NN + 127) / 128;   // 782
    for (int l = 0; l < 3; l++) {
        int K = (l == 0) ? DIN : RANK;
        k_convW<<<(RANK * K + 255) / 256, 256>>>(W[l], K);
        k_gemm_mma<<<mtiles, 512, GEMM_SMEM>>>(K);
        k_agg <<<(NN + NPB - 1) / NPB, 256>>>(b[l]);
        k_bnfinal<<<1, RANK>>>(gamma[l], beta[l]);
        k_pool<<<GG, RANK>>>(out + (size_t)l * GG * RANK);
        if (l < 2)
            k_bnconv<<<(NN * RANK / 4 + 255) / 256, 256>>>();
    }
}

// round 7
// speedup vs baseline: 1.8008x; 1.0491x over previous
#include <cuda_runtime.h>
#include <cuda_bf16.h>
#include <math.h>
#include <stdint.h>

#define NN   100000
#define NPAD 100096          // 782 * 128
#define EE   400000
#define GG   2048
#define DIN  128
#define RANK 256

// ---------------- scratch (device globals: no allocations allowed) ----------
__device__ float g_hw  [NN * RANK];           // GEMM output (fp32)
__device__ __nv_bfloat16 g_ahi[NPAD * RANK];  // A split hi (lda = DIN or RANK)
__device__ __nv_bfloat16 g_alo[NPAD * RANK];  // A split lo
__device__ __nv_bfloat16 g_whi[RANK * RANK];  // (scale-folded) W^T hi  [n][k]
__device__ __nv_bfloat16 g_wlo[RANK * RANK];  // W^T lo
__device__ float g_woff[RANK];                // rank-1 BN offset: shift^T @ W
__device__ int   g_cnt   [NN];
__device__ int   g_cursor[NN];
__device__ int   g_rowptr[NN + 1];
__device__ float g_dinv  [NN];
__device__ int   g_esrc[EE];
__device__ float g_ew  [EE];
__device__ int   g_gptr[GG + 1];
__device__ float g_sum  [RANK];
__device__ float g_sumsq[RANK];
__device__ float g_scale[RANK];
__device__ float g_shift[RANK];
__device__ int   g_part[128];

// ---------------- graph preprocessing (once per call) -----------------------
__global__ void k_init() {
    int i = blockIdx.x * blockDim.x + threadIdx.x;
    if (i < NN) { g_cnt[i] = 0; g_cursor[i] = 0; }
    if (i < RANK) { g_sum[i] = 0.f; g_sumsq[i] = 0.f; g_woff[i] = 0.f; }
}

__global__ void k_hist(const int* __restrict__ dst) {
    int e = blockIdx.x * blockDim.x + threadIdx.x;
    if (e < EE) atomicAdd(&g_cnt[dst[e]], 1);
}

__global__ void k_dinv() {
    int v = blockIdx.x * blockDim.x + threadIdx.x;
    if (v == 0) g_rowptr[NN] = EE;
    if (v < NN) g_dinv[v] = rsqrtf((float)(g_cnt[v] + 1));  // +1 self loop
}

__global__ void k_scan1() {
    __shared__ int sm[256];
    int b = blockIdx.x, t = threadIdx.x;
    int base = b * 1024 + t * 4;
    int s = 0;
    #pragma unroll
    for (int j = 0; j < 4; j++) { int i = base + j; if (i < NN) s += g_cnt[i]; }
    sm[t] = s; __syncthreads();
    for (int off = 128; off > 0; off >>= 1) {
        if (t < off) sm[t] += sm[t + off];
        __syncthreads();
    }
    if (t == 0) g_part[b] = sm[0];
}

__global__ void k_scan2() {
    __shared__ int sm[128];
    int t = threadIdx.x;
    int v = (t < 98) ? g_part[t] : 0;
    sm[t] = v; __syncthreads();
    for (int off = 1; off < 128; off <<= 1) {
        int u = (t >= off) ? sm[t - off] : 0;
        __syncthreads();
        sm[t] += u;
        __syncthreads();
    }
    if (t < 98) g_part[t] = sm[t] - v;   // exclusive
}

__global__ void k_scan3() {
    __shared__ int sm[256];
    int b = blockIdx.x, t = threadIdx.x;
    int base = b * 1024 + t * 4;
    int v[4]; int s = 0;
    #pragma unroll
    for (int j = 0; j < 4; j++) { int i = base + j; v[j] = (i < NN) ? g_cnt[i] : 0; s += v[j]; }
    sm[t] = s; __syncthreads();
    for (int off = 1; off < 256; off <<= 1) {
        int u = (t >= off) ? sm[t - off] : 0;
        __syncthreads();
        sm[t] += u;
        __syncthreads();
    }
    int off0 = g_part[b] + (sm[t] - s);
    int run = 0;
    #pragma unroll
    for (int j = 0; j < 4; j++) {
        int i = base + j;
        if (i < NN) g_rowptr[i] = off0 + run;
        run += v[j];
    }
}

__global__ void k_gptr(const int* __restrict__ batch) {
    int i = blockIdx.x * blockDim.x + threadIdx.x;
    if (i >= NN) return;
    int bi = batch[i];
    if (i == 0) {
        for (int g = 0; g <= bi; g++) g_gptr[g] = 0;
    } else {
        int bp = batch[i - 1];
        for (int g = bp + 1; g <= bi; g++) g_gptr[g] = i;
    }
    if (i == NN - 1) {
        for (int g = bi + 1; g <= GG; g++) g_gptr[g] = NN;
    }
}

__global__ void k_scatter(const int* __restrict__ src, const int* __restrict__ dst) {
    int e = blockIdx.x * blockDim.x + threadIdx.x;
    if (e >= EE) return;
    int s = src[e], d = dst[e];
    int pos = g_rowptr[d] + atomicAdd(&g_cursor[d], 1);
    g_esrc[pos] = s;
    g_ew[pos]   = g_dinv[s] * g_dinv[d];
}

// ---------------- bf16 split conversions -------------------------------------
__device__ __forceinline__ void bf16_split(float v, __nv_bfloat16& hi, __nv_bfloat16& lo) {
    hi = __float2bfloat16(v);
    lo = __float2bfloat16(v - __bfloat162float(hi));
}

// W[K x RANK] row-major -> W'^T [RANK x K] K-major, split hi/lo.
// useSc: fold BN column-scale of the *input* (scale[k]) into W rows.
__global__ void k_convW(const float* __restrict__ W, int K, int useSc) {
    int i = blockIdx.x * blockDim.x + threadIdx.x;   // i over RANK*K
    if (i >= RANK * K) return;
    int n = i / K, k = i - n * K;
    float v = W[(size_t)k * RANK + n];
    if (useSc) v *= g_scale[k];
    __nv_bfloat16 hi, lo; bf16_split(v, hi, lo);
    g_whi[i] = hi; g_wlo[i] = lo;
}

// g_woff[n] += sum_k shift[k] * W[k][n]   (32 blocks over k-ranges, atomics)
__global__ void k_offset(const float* __restrict__ W, int K) {
    int n = threadIdx.x;
    int k0 = blockIdx.x * (K / 32);
    float o = 0.f;
    for (int k = k0; k < k0 + K / 32; k++)
        o = fmaf(g_shift[k], W[(size_t)k * RANK + n], o);
    atomicAdd(&g_woff[n], o);
}

// x [NN x DIN] fp32 -> g_ahi/g_alo packed (lda = DIN)
__global__ void k_convX(const float* __restrict__ x) {
    int i4 = blockIdx.x * blockDim.x + threadIdx.x;  // float4 index
    if (i4 >= NN * DIN / 4) return;
    float4 v = ((const float4*)x)[i4];
    __align__(8) __nv_bfloat16 hh[4], ll[4];
    bf16_split(v.x, hh[0], ll[0]); bf16_split(v.y, hh[1], ll[1]);
    bf16_split(v.z, hh[2], ll[2]); bf16_split(v.w, hh[3], ll[3]);
    *(uint2*)(g_ahi + (size_t)i4 * 4) = *(uint2*)hh;
    *(uint2*)(g_alo + (size_t)i4 * 4) = *(uint2*)ll;
}

// ---------------- mma.sync bf16-split GEMM (double-buffered cp.async) --------
// g_hw[tile] = A(hi,lo) @ W'(hi,lo)^T (3 terms, fp32 accum) + g_woff[col]
#define ASTRIDE 72   // padded bf16 row stride (144B)
#define SA_ELEM (128 * ASTRIDE)
#define SB_ELEM (256 * ASTRIDE)
#define BUF_BYTES ((2 * SA_ELEM + 2 * SB_ELEM) * 2)     // 110592
#define GEMM_SMEM (2 * BUF_BYTES)                        // 221184

#define CP16(dst, src) do {                                                \
    uint32_t _d = (uint32_t)__cvta_generic_to_shared(dst);                 \
    asm volatile("cp.async.cg.shared.global [%0], [%1], 16;"               \
                 :: "r"(_d), "l"(src));                                    \
} while (0)

#define MMA16816(C, A, B) \
    asm volatile("mma.sync.aligned.m16n8k16.row.col.f32.bf16.bf16.f32 " \
        "{%0,%1,%2,%3}, {%4,%5,%6,%7}, {%8,%9}, {%0,%1,%2,%3};" \
        : "+f"((C)[0]), "+f"((C)[1]), "+f"((C)[2]), "+f"((C)[3]) \
        : "r"((A)[0]), "r"((A)[1]), "r"((A)[2]), "r"((A)[3]), \
          "r"((B)[0]), "r"((B)[1]))

__global__ void __launch_bounds__(512, 1)
k_gemm_mma(int K) {
    extern __shared__ __align__(16) char smem[];

    int tid = threadIdx.x;
    int wid = tid >> 5, lid = tid & 31;
    int m0  = blockIdx.x * 128;
    int wm  = (wid & 1) * 64;
    int wn  = (wid >> 1) * 32;
    int lr  = lid >> 2;
    int lc  = lid & 3;

    float c[4][4][4];
    #pragma unroll
    for (int i = 0; i < 4; i++)
        #pragma unroll
        for (int j = 0; j < 4; j++)
            #pragma unroll
            for (int q = 0; q < 4; q++) c[i][j][q] = 0.f;

    auto load_chunk = [&](int kc, char* base) {
        __nv_bfloat16* sAh = (__nv_bfloat16*)base;
        __nv_bfloat16* sAl = sAh + SA_ELEM;
        __nv_bfloat16* sBh = sAl + SA_ELEM;
        __nv_bfloat16* sBl = sBh + SB_ELEM;
        #pragma unroll
        for (int j = 0; j < 2; j++) {
            int i = tid * 2 + j;
            int r = i >> 3, kg = i & 7;
            size_t go = (size_t)(m0 + r) * K + kc + kg * 8;
            CP16(sAh + r * ASTRIDE + kg * 8, g_ahi + go);
            CP16(sAl + r * ASTRIDE + kg * 8, g_alo + go);
        }
        #pragma unroll
        for (int j = 0; j < 4; j++) {
            int i = tid * 4 + j;
            int n = i >> 3, kg = i & 7;
            size_t go = (size_t)n * K + kc + kg * 8;
            CP16(sBh + n * ASTRIDE + kg * 8, g_whi + go);
            CP16(sBl + n * ASTRIDE + kg * 8, g_wlo + go);
        }
        asm volatile("cp.async.commit_group;" ::: "memory");
    };

    int nch = K >> 6;
    load_chunk(0, smem);

    for (int kc = 0; kc < nch; kc++) {
        if (kc + 1 < nch) {
            load_chunk((kc + 1) << 6, smem + ((kc + 1) & 1) * BUF_BYTES);
            asm volatile("cp.async.wait_group 1;" ::: "memory");
        } else {
            asm volatile("cp.async.wait_group 0;" ::: "memory");
        }
        __syncthreads();

        char* base = smem + (kc & 1) * BUF_BYTES;
        __nv_bfloat16* sAh = (__nv_bfloat16*)base;
        __nv_bfloat16* sAl = sAh + SA_ELEM;
        __nv_bfloat16* sBh = sAl + SA_ELEM;
        __nv_bfloat16* sBl = sBh + SB_ELEM;

        #pragma unroll
        for (int ks = 0; ks < 4; ks++) {
            int koff = ks * 16 + lc * 2;
            uint32_t bh[4][2], bl[4][2];
            #pragma unroll
            for (int fn = 0; fn < 4; fn++) {
                int n = wn + fn * 8 + lr;
                bh[fn][0] = *(const uint32_t*)(sBh + n * ASTRIDE + koff);
                bh[fn][1] = *(const uint32_t*)(sBh + n * ASTRIDE + koff + 8);
                bl[fn][0] = *(const uint32_t*)(sBl + n * ASTRIDE + koff);
                bl[fn][1] = *(const uint32_t*)(sBl + n * ASTRIDE + koff + 8);
            }
            #pragma unroll
            for (int fm = 0; fm < 4; fm++) {
                int m = wm + fm * 16 + lr;
                uint32_t ah[4], al[4];
                ah[0] = *(const uint32_t*)(sAh + m * ASTRIDE + koff);
                ah[1] = *(const uint32_t*)(sAh + (m + 8) * ASTRIDE + koff);
                ah[2] = *(const uint32_t*)(sAh + m * ASTRIDE + koff + 8);
                ah[3] = *(const uint32_t*)(sAh + (m + 8) * ASTRIDE + koff + 8);
                al[0] = *(const uint32_t*)(sAl + m * ASTRIDE + koff);
                al[1] = *(const uint32_t*)(sAl + (m + 8) * ASTRIDE + koff);
                al[2] = *(const uint32_t*)(sAl + m * ASTRIDE + koff + 8);
                al[3] = *(const uint32_t*)(sAl + (m + 8) * ASTRIDE + koff + 8);
                #pragma unroll
                for (int fn = 0; fn < 4; fn++) {
                    MMA16816(c[fm][fn], ah, bh[fn]);
                    MMA16816(c[fm][fn], ah, bl[fn]);
                    MMA16816(c[fm][fn], al, bh[fn]);
                }
            }
        }
        __syncthreads();
    }

    // epilogue: fragment + rank-1 BN offset -> g_hw
    #pragma unroll
    for (int fm = 0; fm < 4; fm++) {
        int r0 = m0 + wm + fm * 16 + lr;
        int r1 = r0 + 8;
        #pragma unroll
        for (int fn = 0; fn < 4; fn++) {
            int col = wn + fn * 8 + lc * 2;
            float o0 = g_woff[col], o1 = g_woff[col + 1];
            if (r0 < NN)
                *(float2*)(g_hw + (size_t)r0 * RANK + col) =
                    make_float2(c[fm][fn][0] + o0, c[fm][fn][1] + o1);
            if (r1 < NN)
                *(float2*)(g_hw + (size_t)r1 * RANK + col) =
                    make_float2(c[fm][fn][2] + o0, c[fm][fn][3] + o1);
        }
    }
}

// ---------------- aggregation + bias + tanh + BN stats + bf16 split ---------
#define NPB 32
__global__ void __launch_bounds__(256)
k_agg(const float* __restrict__ bias) {
    __shared__ float ssum[RANK], ssq[RANK];
    int tid = threadIdx.x;
    int cg  = (tid & 63) * 4;
    int sub = tid >> 6;
    if (tid < RANK) { ssum[tid] = 0.f; ssq[tid] = 0.f; }
    __syncthreads();

    float4 bc = *(const float4*)(bias + cg);
    float s0 = 0.f, s1 = 0.f, s2v = 0.f, s3 = 0.f;
    float q0 = 0.f, q1 = 0.f, q2 = 0.f, q3 = 0.f;
    int v0 = blockIdx.x * NPB;

    for (int n = sub; n < NPB; n += 4) {
        int v = v0 + n;
        if (v >= NN) break;
        int beg = g_rowptr[v], end = g_rowptr[v + 1];
        float di = g_dinv[v];
        float w0 = di * di;
        float4 hv = *(const float4*)(g_hw + (size_t)v * RANK + cg);
        float4 acc = make_float4(w0 * hv.x, w0 * hv.y, w0 * hv.z, w0 * hv.w);

        int e = beg;
        for (; e + 4 <= end; e += 4) {
            float w0e = g_ew[e],     w1e = g_ew[e + 1];
            float w2e = g_ew[e + 2], w3e = g_ew[e + 3];
            int   i0 = g_esrc[e],     i1 = g_esrc[e + 1];
            int   i2 = g_esrc[e + 2], i3 = g_esrc[e + 3];
            float4 r0 = *(const float4*)(g_hw + (size_t)i0 * RANK + cg);
            float4 r1 = *(const float4*)(g_hw + (size_t)i1 * RANK + cg);
            float4 r2 = *(const float4*)(g_hw + (size_t)i2 * RANK + cg);
            float4 r3 = *(const float4*)(g_hw + (size_t)i3 * RANK + cg);
            acc.x = fmaf(w0e, r0.x, acc.x); acc.y = fmaf(w0e, r0.y, acc.y);
            acc.z = fmaf(w0e, r0.z, acc.z); acc.w = fmaf(w0e, r0.w, acc.w);
            acc.x = fmaf(w1e, r1.x, acc.x); acc.y = fmaf(w1e, r1.y, acc.y);
            acc.z = fmaf(w1e, r1.z, acc.z); acc.w = fmaf(w1e, r1.w, acc.w);
            acc.x = fmaf(w2e, r2.x, acc.x); acc.y = fmaf(w2e, r2.y, acc.y);
            acc.z = fmaf(w2e, r2.z, acc.z); acc.w = fmaf(w2e, r2.w, acc.w);
            acc.x = fmaf(w3e, r3.x, acc.x); acc.y = fmaf(w3e, r3.y, acc.y);
            acc.z = fmaf(w3e, r3.z, acc.z); acc.w = fmaf(w3e, r3.w, acc.w);
        }
        for (; e < end; e++) {
            float w = g_ew[e];
            const float4 hs = *(const float4*)(g_hw + (size_t)g_esrc[e] * RANK + cg);
            acc.x = fmaf(w, hs.x, acc.x); acc.y = fmaf(w, hs.y, acc.y);
            acc.z = fmaf(w, hs.z, acc.z); acc.w = fmaf(w, hs.w, acc.w);
        }

        float4 h;
        h.x = tanhf(acc.x + bc.x);
        h.y = tanhf(acc.y + bc.y);
        h.z = tanhf(acc.z + bc.z);
        h.w = tanhf(acc.w + bc.w);

        // write bf16 hi/lo split (next GEMM A operand / pool input)
        __align__(8) __nv_bfloat16 hh[4], ll[4];
        bf16_split(h.x, hh[0], ll[0]); bf16_split(h.y, hh[1], ll[1]);
        bf16_split(h.z, hh[2], ll[2]); bf16_split(h.w, hh[3], ll[3]);
        *(uint2*)(g_ahi + (size_t)v * RANK + cg) = *(uint2*)hh;
        *(uint2*)(g_alo + (size_t)v * RANK + cg) = *(uint2*)ll;

        s0 += h.x; s1 += h.y; s2v += h.z; s3 += h.w;
        q0 = fmaf(h.x, h.x, q0); q1 = fmaf(h.y, h.y, q1);
        q2 = fmaf(h.z, h.z, q2); q3 = fmaf(h.w, h.w, q3);
    }

    atomicAdd(&ssum[cg + 0], s0);  atomicAdd(&ssq[cg + 0], q0);
    atomicAdd(&ssum[cg + 1], s1);  atomicAdd(&ssq[cg + 1], q1);
    atomicAdd(&ssum[cg + 2], s2v); atomicAdd(&ssq[cg + 2], q2);
    atomicAdd(&ssum[cg + 3], s3);  atomicAdd(&ssq[cg + 3], q3);
    __syncthreads();
    if (tid < RANK) {
        atomicAdd(&g_sum[tid],   ssum[tid]);
        atomicAdd(&g_sumsq[tid], ssq[tid]);
    }
}

__global__ void k_bnfinal(const float* __restrict__ gamma,
                          const float* __restrict__ beta) {
    int c = threadIdx.x;
    float mu  = g_sum[c]   * (1.0f / NN);
    float var = g_sumsq[c] * (1.0f / NN) - mu * mu;
    float sc  = gamma[c] * rsqrtf(var + 1e-5f);
    g_scale[c] = sc;
    g_shift[c] = beta[c] - mu * sc;
    g_sum[c] = 0.f; g_sumsq[c] = 0.f;
    g_woff[c] = 0.f;                 // ready for next layer's k_offset
}

__global__ void k_pool(float* __restrict__ out) {
    int g = blockIdx.x, c = threadIdx.x;
    int beg = g_gptr[g], end = g_gptr[g + 1];
    float sc = g_scale[c], sh = g_shift[c];
    float m = -INFINITY;
    for (int r = beg; r < end; r++) {
        size_t off = (size_t)r * RANK + c;
        float h = __bfloat162float(g_ahi[off]) + __bfloat162float(g_alo[off]);
        m = fmaxf(m, fmaf(sc, h, sh));
    }
    out[(size_t)g * RANK + c] = (end > beg) ? m : 0.0f;
}

// ---------------- launch ----------------------------------------------------
extern "C" void kernel_launch(void* const* d_in, const int* in_sizes, int n_in,
                              void* d_out, int out_size) {
    const float* x     = (const float*)d_in[0];
    const int*   ei    = (const int*)  d_in[1];   // [2, E] int32
    const int*   batch = (const int*)  d_in[2];
    const float* W[3]     = { (const float*)d_in[3],  (const float*)d_in[7],  (const float*)d_in[11] };
    const float* b[3]     = { (const float*)d_in[4],  (const float*)d_in[8],  (const float*)d_in[12] };
    const float* gamma[3] = { (const float*)d_in[5],  (const float*)d_in[9],  (const float*)d_in[13] };
    const float* beta[3]  = { (const float*)d_in[6],  (const float*)d_in[10], (const float*)d_in[14] };
    const int* src = ei;
    const int* dst = ei + EE;
    float* out = (float*)d_out;

    cudaFuncSetAttribute(k_gemm_mma, cudaFuncAttributeMaxDynamicSharedMemorySize, GEMM_SMEM);

    k_init   <<<(NN + 255) / 256, 256>>>();
    k_hist   <<<(EE + 255) / 256, 256>>>(dst);
    k_dinv   <<<(NN + 255) / 256, 256>>>();
    k_scan1  <<<98, 256>>>();
    k_scan2  <<<1, 128>>>();
    k_scan3  <<<98, 256>>>();
    k_gptr   <<<(NN + 255) / 256, 256>>>(batch);
    k_scatter<<<(EE + 255) / 256, 256>>>(src, dst);
    k_convX  <<<(NN * DIN / 4 + 255) / 256, 256>>>(x);

    int mtiles = (NN + 127) / 128;   // 782
    for (int l = 0; l < 3; l++) {
        int K = (l == 0) ? DIN : RANK;
        k_convW<<<(RANK * K + 255) / 256, 256>>>(W[l], K, l > 0);
        if (l > 0) k_offset<<<32, RANK>>>(W[l], K);
        k_gemm_mma<<<mtiles, 512, GEMM_SMEM>>>(K);
        k_agg <<<(NN + NPB - 1) / NPB, 256>>>(b[l]);
        k_bnfinal<<<1, RANK>>>(gamma[l], beta[l]);
        k_pool<<<GG, RANK>>>(out + (size_t)l * GG * RANK);
    }
}

// round 8
// speedup vs baseline: 2.2453x; 1.2468x over previous
#include <cuda_runtime.h>
#include <cuda_bf16.h>
#include <cuda_fp16.h>
#include <math.h>
#include <stdint.h>

#define NN   100000
#define NPAD 100096          // 782 * 128
#define EE   400000
#define GG   2048
#define DIN  128
#define RANK 256

// ---------------- scratch (device globals: no allocations allowed) ----------
__device__ __half g_hf16[NPAD * RANK];        // h (tanh out) fp16; also x fp16 (lda=DIN)
__device__ __nv_bfloat16 g_ahi[NPAD * RANK];  // Agg(h) split hi (lda = K)
__device__ __nv_bfloat16 g_alo[NPAD * RANK];  // Agg(h) split lo
__device__ __nv_bfloat16 g_whi[RANK * RANK];  // (scale-folded) W^T hi  [n][k]
__device__ __nv_bfloat16 g_wlo[RANK * RANK];  // W^T lo
__device__ float g_woff[RANK];                // rank-1 BN offset: shift^T @ W
__device__ float g_rho [NN];                  // per-node aggregation of ones
__device__ float g_rhop[NN];
__device__ int   g_cnt   [NN];
__device__ int   g_cursor[NN];
__device__ int   g_rowptr[NN + 1];
__device__ float g_dinv  [NN];
__device__ int   g_esrc[EE];
__device__ float g_ew  [EE];
__device__ int   g_gptr[GG + 1];
__device__ float g_sum  [RANK];
__device__ float g_sumsq[RANK];
__device__ float g_scale[RANK];
__device__ float g_shift[RANK];
__device__ int   g_part[128];

// ---------------- graph preprocessing (once per call) -----------------------
__global__ void k_init() {
    int i = blockIdx.x * blockDim.x + threadIdx.x;
    if (i < NN) { g_cnt[i] = 0; g_cursor[i] = 0; g_rhop[i] = 0.f; }
    if (i < RANK) { g_sum[i] = 0.f; g_sumsq[i] = 0.f; g_woff[i] = 0.f; }
}

__global__ void k_hist(const int* __restrict__ dst) {
    int e = blockIdx.x * blockDim.x + threadIdx.x;
    if (e < EE) atomicAdd(&g_cnt[dst[e]], 1);
}

__global__ void k_dinv() {
    int v = blockIdx.x * blockDim.x + threadIdx.x;
    if (v == 0) g_rowptr[NN] = EE;
    if (v < NN) g_dinv[v] = rsqrtf((float)(g_cnt[v] + 1));  // +1 self loop
}

__global__ void k_scan1() {
    __shared__ int sm[256];
    int b = blockIdx.x, t = threadIdx.x;
    int base = b * 1024 + t * 4;
    int s = 0;
    #pragma unroll
    for (int j = 0; j < 4; j++) { int i = base + j; if (i < NN) s += g_cnt[i]; }
    sm[t] = s; __syncthreads();
    for (int off = 128; off > 0; off >>= 1) {
        if (t < off) sm[t] += sm[t + off];
        __syncthreads();
    }
    if (t == 0) g_part[b] = sm[0];
}

__global__ void k_scan2() {
    __shared__ int sm[128];
    int t = threadIdx.x;
    int v = (t < 98) ? g_part[t] : 0;
    sm[t] = v; __syncthreads();
    for (int off = 1; off < 128; off <<= 1) {
        int u = (t >= off) ? sm[t - off] : 0;
        __syncthreads();
        sm[t] += u;
        __syncthreads();
    }
    if (t < 98) g_part[t] = sm[t] - v;   // exclusive
}

__global__ void k_scan3() {
    __shared__ int sm[256];
    int b = blockIdx.x, t = threadIdx.x;
    int base = b * 1024 + t * 4;
    int v[4]; int s = 0;
    #pragma unroll
    for (int j = 0; j < 4; j++) { int i = base + j; v[j] = (i < NN) ? g_cnt[i] : 0; s += v[j]; }
    sm[t] = s; __syncthreads();
    for (int off = 1; off < 256; off <<= 1) {
        int u = (t >= off) ? sm[t - off] : 0;
        __syncthreads();
        sm[t] += u;
        __syncthreads();
    }
    int off0 = g_part[b] + (sm[t] - s);
    int run = 0;
    #pragma unroll
    for (int j = 0; j < 4; j++) {
        int i = base + j;
        if (i < NN) g_rowptr[i] = off0 + run;
        run += v[j];
    }
}

__global__ void k_gptr(const int* __restrict__ batch) {
    int i = blockIdx.x * blockDim.x + threadIdx.x;
    if (i >= NN) return;
    int bi = batch[i];
    if (i == 0) {
        for (int g = 0; g <= bi; g++) g_gptr[g] = 0;
    } else {
        int bp = batch[i - 1];
        for (int g = bp + 1; g <= bi; g++) g_gptr[g] = i;
    }
    if (i == NN - 1) {
        for (int g = bi + 1; g <= GG; g++) g_gptr[g] = NN;
    }
}

__global__ void k_scatter(const int* __restrict__ src, const int* __restrict__ dst) {
    int e = blockIdx.x * blockDim.x + threadIdx.x;
    if (e >= EE) return;
    int s = src[e], d = dst[e];
    int pos = g_rowptr[d] + atomicAdd(&g_cursor[d], 1);
    float ds = g_dinv[s];
    g_esrc[pos] = s;
    g_ew[pos]   = ds * g_dinv[d];
    atomicAdd(&g_rhop[d], ds);
}

__global__ void k_rhofin() {
    int v = blockIdx.x * blockDim.x + threadIdx.x;
    if (v < NN) {
        float di = g_dinv[v];
        g_rho[v] = di * (g_rhop[v] + di);
    }
}

// ---------------- conversions ------------------------------------------------
__device__ __forceinline__ void bf16_split(float v, __nv_bfloat16& hi, __nv_bfloat16& lo) {
    hi = __float2bfloat16(v);
    lo = __float2bfloat16(v - __bfloat162float(hi));
}

// W[K x RANK] row-major -> W'^T [RANK x K] K-major, split hi/lo (fold scale)
__global__ void k_convW(const float* __restrict__ W, int K, int useSc) {
    int i = blockIdx.x * blockDim.x + threadIdx.x;
    if (i >= RANK * K) return;
    int n = i / K, k = i - n * K;
    float v = W[(size_t)k * RANK + n];
    if (useSc) v *= g_scale[k];
    __nv_bfloat16 hi, lo; bf16_split(v, hi, lo);
    g_whi[i] = hi; g_wlo[i] = lo;
}

// g_woff[n] += sum_k shift[k] * W[k][n]
__global__ void k_offset(const float* __restrict__ W, int K) {
    int n = threadIdx.x;
    int k0 = blockIdx.x * (K / 32);
    float o = 0.f;
    for (int k = k0; k < k0 + K / 32; k++)
        o = fmaf(g_shift[k], W[(size_t)k * RANK + n], o);
    atomicAdd(&g_woff[n], o);
}

// x [NN x DIN] fp32 -> fp16 into g_hf16 (lda = DIN)
__global__ void k_convX16(const float* __restrict__ x) {
    int i4 = blockIdx.x * blockDim.x + threadIdx.x;
    if (i4 >= NN * DIN / 4) return;
    float4 v = ((const float4*)x)[i4];
    __half2 a = __floats2half2_rn(v.x, v.y);
    __half2 b = __floats2half2_rn(v.z, v.w);
    *(uint2*)(g_hf16 + (size_t)i4 * 4) = make_uint2(*(uint32_t*)&a, *(uint32_t*)&b);
}

// ---------------- aggregation of fp16 h -> bf16 hi/lo split -----------------
// acc[v] = dinv^2 h[v] + sum_e w_e h[src]; output split to g_ahi/g_alo (lda=K)
#define ANPB 16
__global__ void __launch_bounds__(256)
k_aggH(int K) {
    int ncg  = K >> 3;               // 16B column groups (8 halves)
    int tid  = threadIdx.x;
    int cg   = (tid & (ncg - 1)) * 8;
    int sub  = tid / ncg;
    int nsub = 256 / ncg;
    int v0   = blockIdx.x * ANPB;

    for (int n = sub; n < ANPB; n += nsub) {
        int v = v0 + n;
        if (v >= NN) break;
        int beg = g_rowptr[v], end = g_rowptr[v + 1];
        float di = g_dinv[v];
        float w0 = di * di;

        float acc[8];
        {
            uint4 u = *(const uint4*)(g_hf16 + (size_t)v * K + cg);
            const __half2* hp = (const __half2*)&u;
            #pragma unroll
            for (int j = 0; j < 4; j++) {
                float2 f = __half22float2(hp[j]);
                acc[2 * j]     = w0 * f.x;
                acc[2 * j + 1] = w0 * f.y;
            }
        }
        int e = beg;
        for (; e + 2 <= end; e += 2) {
            float w1 = g_ew[e], w2 = g_ew[e + 1];
            int   s1 = g_esrc[e], s2 = g_esrc[e + 1];
            uint4 u1 = *(const uint4*)(g_hf16 + (size_t)s1 * K + cg);
            uint4 u2 = *(const uint4*)(g_hf16 + (size_t)s2 * K + cg);
            const __half2* h1 = (const __half2*)&u1;
            const __half2* h2 = (const __half2*)&u2;
            #pragma unroll
            for (int j = 0; j < 4; j++) {
                float2 f1 = __half22float2(h1[j]);
                float2 f2 = __half22float2(h2[j]);
                acc[2 * j]     = fmaf(w1, f1.x, acc[2 * j]);
                acc[2 * j + 1] = fmaf(w1, f1.y, acc[2 * j + 1]);
                acc[2 * j]     = fmaf(w2, f2.x, acc[2 * j]);
                acc[2 * j + 1] = fmaf(w2, f2.y, acc[2 * j + 1]);
            }
        }
        for (; e < end; e++) {
            float w = g_ew[e];
            int   s = g_esrc[e];
            uint4 u = *(const uint4*)(g_hf16 + (size_t)s * K + cg);
            const __half2* hp = (const __half2*)&u;
            #pragma unroll
            for (int j = 0; j < 4; j++) {
                float2 f = __half22float2(hp[j]);
                acc[2 * j]     = fmaf(w, f.x, acc[2 * j]);
                acc[2 * j + 1] = fmaf(w, f.y, acc[2 * j + 1]);
            }
        }

        __align__(16) __nv_bfloat16 hi[8], lo[8];
        #pragma unroll
        for (int j = 0; j < 8; j++) bf16_split(acc[j], hi[j], lo[j]);
        *(uint4*)(g_ahi + (size_t)v * K + cg) = *(uint4*)hi;
        *(uint4*)(g_alo + (size_t)v * K + cg) = *(uint4*)lo;
    }
}

// ---------------- mma.sync bf16-split GEMM + fused tanh/BN-stat epilogue ----
#define ASTRIDE 72
#define SA_ELEM (128 * ASTRIDE)
#define SB_ELEM (256 * ASTRIDE)
#define BUF_BYTES ((2 * SA_ELEM + 2 * SB_ELEM) * 2)     // 110592
#define GEMM_SMEM (2 * BUF_BYTES)                        // 221184

#define CP16(dst, src) do {                                                \
    uint32_t _d = (uint32_t)__cvta_generic_to_shared(dst);                 \
    asm volatile("cp.async.cg.shared.global [%0], [%1], 16;"               \
                 :: "r"(_d), "l"(src));                                    \
} while (0)

#define MMA16816(C, A, B) \
    asm volatile("mma.sync.aligned.m16n8k16.row.col.f32.bf16.bf16.f32 " \
        "{%0,%1,%2,%3}, {%4,%5,%6,%7}, {%8,%9}, {%0,%1,%2,%3};" \
        : "+f"((C)[0]), "+f"((C)[1]), "+f"((C)[2]), "+f"((C)[3]) \
        : "r"((A)[0]), "r"((A)[1]), "r"((A)[2]), "r"((A)[3]), \
          "r"((B)[0]), "r"((B)[1]))

__global__ void __launch_bounds__(512, 1)
k_gemm_mma(int K, const float* __restrict__ bias) {
    extern __shared__ __align__(16) char smem[];

    int tid = threadIdx.x;
    int wid = tid >> 5, lid = tid & 31;
    int m0  = blockIdx.x * 128;
    int wm  = (wid & 1) * 64;
    int wn  = (wid >> 1) * 32;
    int lr  = lid >> 2;
    int lc  = lid & 3;

    float c[4][4][4];
    #pragma unroll
    for (int i = 0; i < 4; i++)
        #pragma unroll
        for (int j = 0; j < 4; j++)
            #pragma unroll
            for (int q = 0; q < 4; q++) c[i][j][q] = 0.f;

    auto load_chunk = [&](int kc, char* base) {
        __nv_bfloat16* sAh = (__nv_bfloat16*)base;
        __nv_bfloat16* sAl = sAh + SA_ELEM;
        __nv_bfloat16* sBh = sAl + SA_ELEM;
        __nv_bfloat16* sBl = sBh + SB_ELEM;
        #pragma unroll
        for (int j = 0; j < 2; j++) {
            int i = tid * 2 + j;
            int r = i >> 3, kg = i & 7;
            size_t go = (size_t)(m0 + r) * K + kc + kg * 8;
            CP16(sAh + r * ASTRIDE + kg * 8, g_ahi + go);
            CP16(sAl + r * ASTRIDE + kg * 8, g_alo + go);
        }
        #pragma unroll
        for (int j = 0; j < 4; j++) {
            int i = tid * 4 + j;
            int n = i >> 3, kg = i & 7;
            size_t go = (size_t)n * K + kc + kg * 8;
            CP16(sBh + n * ASTRIDE + kg * 8, g_whi + go);
            CP16(sBl + n * ASTRIDE + kg * 8, g_wlo + go);
        }
        asm volatile("cp.async.commit_group;" ::: "memory");
    };

    int nch = K >> 6;
    load_chunk(0, smem);

    for (int kc = 0; kc < nch; kc++) {
        if (kc + 1 < nch) {
            load_chunk((kc + 1) << 6, smem + ((kc + 1) & 1) * BUF_BYTES);
            asm volatile("cp.async.wait_group 1;" ::: "memory");
        } else {
            asm volatile("cp.async.wait_group 0;" ::: "memory");
        }
        __syncthreads();

        char* base = smem + (kc & 1) * BUF_BYTES;
        __nv_bfloat16* sAh = (__nv_bfloat16*)base;
        __nv_bfloat16* sAl = sAh + SA_ELEM;
        __nv_bfloat16* sBh = sAl + SA_ELEM;
        __nv_bfloat16* sBl = sBh + SB_ELEM;

        #pragma unroll
        for (int ks = 0; ks < 4; ks++) {
            int koff = ks * 16 + lc * 2;
            uint32_t bh[4][2], bl[4][2];
            #pragma unroll
            for (int fn = 0; fn < 4; fn++) {
                int n = wn + fn * 8 + lr;
                bh[fn][0] = *(const uint32_t*)(sBh + n * ASTRIDE + koff);
                bh[fn][1] = *(const uint32_t*)(sBh + n * ASTRIDE + koff + 8);
                bl[fn][0] = *(const uint32_t*)(sBl + n * ASTRIDE + koff);
                bl[fn][1] = *(const uint32_t*)(sBl + n * ASTRIDE + koff + 8);
            }
            #pragma unroll
            for (int fm = 0; fm < 4; fm++) {
                int m = wm + fm * 16 + lr;
                uint32_t ah[4], al[4];
                ah[0] = *(const uint32_t*)(sAh + m * ASTRIDE + koff);
                ah[1] = *(const uint32_t*)(sAh + (m + 8) * ASTRIDE + koff);
                ah[2] = *(const uint32_t*)(sAh + m * ASTRIDE + koff + 8);
                ah[3] = *(const uint32_t*)(sAh + (m + 8) * ASTRIDE + koff + 8);
                al[0] = *(const uint32_t*)(sAl + m * ASTRIDE + koff);
                al[1] = *(const uint32_t*)(sAl + (m + 8) * ASTRIDE + koff);
                al[2] = *(const uint32_t*)(sAl + m * ASTRIDE + koff + 8);
                al[3] = *(const uint32_t*)(sAl + (m + 8) * ASTRIDE + koff + 8);
                #pragma unroll
                for (int fn = 0; fn < 4; fn++) {
                    MMA16816(c[fm][fn], ah, bh[fn]);
                    MMA16816(c[fm][fn], ah, bl[fn]);
                    MMA16816(c[fm][fn], al, bh[fn]);
                }
            }
        }
        __syncthreads();
    }

    // ---- fused epilogue: y = acc + rho*woff + bias; h = tanh(y) ----
    float woffv[8], biasv[8];
    #pragma unroll
    for (int fn = 0; fn < 4; fn++) {
        int col = wn + fn * 8 + lc * 2;
        woffv[fn * 2]     = g_woff[col];
        woffv[fn * 2 + 1] = g_woff[col + 1];
        biasv[fn * 2]     = bias[col];
        biasv[fn * 2 + 1] = bias[col + 1];
    }

    float ts[8], tq[8];
    #pragma unroll
    for (int j = 0; j < 8; j++) { ts[j] = 0.f; tq[j] = 0.f; }

    #pragma unroll
    for (int fm = 0; fm < 4; fm++) {
        int r0 = m0 + wm + fm * 16 + lr;
        int r1 = r0 + 8;
        float rho0 = (r0 < NN) ? g_rho[r0] : 0.f;
        float rho1 = (r1 < NN) ? g_rho[r1] : 0.f;
        #pragma unroll
        for (int fn = 0; fn < 4; fn++) {
            int col = wn + fn * 8 + lc * 2;
            float w0v = woffv[fn * 2], w1v = woffv[fn * 2 + 1];
            float b0v = biasv[fn * 2], b1v = biasv[fn * 2 + 1];
            if (r0 < NN) {
                float h00 = tanhf(c[fm][fn][0] + rho0 * w0v + b0v);
                float h01 = tanhf(c[fm][fn][1] + rho0 * w1v + b1v);
                *(__half2*)(g_hf16 + (size_t)r0 * RANK + col) = __floats2half2_rn(h00, h01);
                ts[fn * 2] += h00;     tq[fn * 2]     = fmaf(h00, h00, tq[fn * 2]);
                ts[fn * 2 + 1] += h01; tq[fn * 2 + 1] = fmaf(h01, h01, tq[fn * 2 + 1]);
            }
            if (r1 < NN) {
                float h10 = tanhf(c[fm][fn][2] + rho1 * w0v + b0v);
                float h11 = tanhf(c[fm][fn][3] + rho1 * w1v + b1v);
                *(__half2*)(g_hf16 + (size_t)r1 * RANK + col) = __floats2half2_rn(h10, h11);
                ts[fn * 2] += h10;     tq[fn * 2]     = fmaf(h10, h10, tq[fn * 2]);
                ts[fn * 2 + 1] += h11; tq[fn * 2 + 1] = fmaf(h11, h11, tq[fn * 2 + 1]);
            }
        }
    }

    // warp reduce over lr (lanes differing in bits 2..4)
    #pragma unroll
    for (int off = 4; off < 32; off <<= 1) {
        #pragma unroll
        for (int j = 0; j < 8; j++) {
            ts[j] += __shfl_xor_sync(0xffffffff, ts[j], off);
            tq[j] += __shfl_xor_sync(0xffffffff, tq[j], off);
        }
    }

    float* red = (float*)smem;   // reuse dynamic smem: [0:256) sum, [256:512) sq
    __syncthreads();
    if (tid < RANK) { red[tid] = 0.f; red[RANK + tid] = 0.f; }
    __syncthreads();
    if (lr == 0) {
        #pragma unroll
        for (int fn = 0; fn < 4; fn++) {
            int col = wn + fn * 8 + lc * 2;
            atomicAdd(&red[col],            ts[fn * 2]);
            atomicAdd(&red[col + 1],        ts[fn * 2 + 1]);
            atomicAdd(&red[RANK + col],     tq[fn * 2]);
            atomicAdd(&red[RANK + col + 1], tq[fn * 2 + 1]);
        }
    }
    __syncthreads();
    if (tid < RANK) {
        atomicAdd(&g_sum[tid],   red[tid]);
        atomicAdd(&g_sumsq[tid], red[RANK + tid]);
    }
}

__global__ void k_bnfinal(const float* __restrict__ gamma,
                          const float* __restrict__ beta) {
    int c = threadIdx.x;
    float mu  = g_sum[c]   * (1.0f / NN);
    float var = g_sumsq[c] * (1.0f / NN) - mu * mu;
    float sc  = gamma[c] * rsqrtf(var + 1e-5f);
    g_scale[c] = sc;
    g_shift[c] = beta[c] - mu * sc;
    g_sum[c] = 0.f; g_sumsq[c] = 0.f;
    g_woff[c] = 0.f;
}

__global__ void k_pool(float* __restrict__ out) {
    int g = blockIdx.x, c = threadIdx.x;
    int beg = g_gptr[g], end = g_gptr[g + 1];
    float sc = g_scale[c], sh = g_shift[c];
    float m = -INFINITY;
    for (int r = beg; r < end; r++) {
        float h = __half2float(g_hf16[(size_t)r * RANK + c]);
        m = fmaxf(m, fmaf(sc, h, sh));
    }
    out[(size_t)g * RANK + c] = (end > beg) ? m : 0.0f;
}

// ---------------- launch ----------------------------------------------------
extern "C" void kernel_launch(void* const* d_in, const int* in_sizes, int n_in,
                              void* d_out, int out_size) {
    const float* x     = (const float*)d_in[0];
    const int*   ei    = (const int*)  d_in[1];   // [2, E] int32
    const int*   batch = (const int*)  d_in[2];
    const float* W[3]     = { (const float*)d_in[3],  (const float*)d_in[7],  (const float*)d_in[11] };
    const float* b[3]     = { (const float*)d_in[4],  (const float*)d_in[8],  (const float*)d_in[12] };
    const float* gamma[3] = { (const float*)d_in[5],  (const float*)d_in[9],  (const float*)d_in[13] };
    const float* beta[3]  = { (const float*)d_in[6],  (const float*)d_in[10], (const float*)d_in[14] };
    const int* src = ei;
    const int* dst = ei + EE;
    float* out = (float*)d_out;

    cudaFuncSetAttribute(k_gemm_mma, cudaFuncAttributeMaxDynamicSharedMemorySize, GEMM_SMEM);

    k_init   <<<(NN + 255) / 256, 256>>>();
    k_hist   <<<(EE + 255) / 256, 256>>>(dst);
    k_dinv   <<<(NN + 255) / 256, 256>>>();
    k_scan1  <<<98, 256>>>();
    k_scan2  <<<1, 128>>>();
    k_scan3  <<<98, 256>>>();
    k_gptr   <<<(NN + 255) / 256, 256>>>(batch);
    k_scatter<<<(EE + 255) / 256, 256>>>(src, dst);
    k_rhofin <<<(NN + 255) / 256, 256>>>();
    k_convX16<<<(NN * DIN / 4 + 255) / 256, 256>>>(x);

    int mtiles = (NN + 127) / 128;   // 782
    int ablocks = (NN + ANPB - 1) / ANPB;
    for (int l = 0; l < 3; l++) {
        int K = (l == 0) ? DIN : RANK;
        k_convW<<<(RANK * K + 255) / 256, 256>>>(W[l], K, l > 0);
        if (l > 0) k_offset<<<32, RANK>>>(W[l], K);
        k_aggH<<<ablocks, 256>>>(K);
        k_gemm_mma<<<mtiles, 512, GEMM_SMEM>>>(K, b[l]);
        k_bnfinal<<<1, RANK>>>(gamma[l], beta[l]);
        k_pool<<<GG, RANK>>>(out + (size_t)l * GG * RANK);
    }
}

// round 9
// speedup vs baseline: 2.7361x; 1.2186x over previous
#include <cuda_runtime.h>
#include <cuda_fp16.h>
#include <math.h>
#include <stdint.h>

#define NN   100000
#define NPAD 100096          // 782 * 128
#define EE   400000
#define GG   2048
#define DIN  128
#define RANK 256

// ---------------- scratch (device globals: no allocations allowed) ----------
__device__ __half g_hf16[NPAD * RANK];   // h (tanh out) fp16; also x fp16 (lda=K)
__device__ __half g_ahi[NPAD * RANK];    // Agg(h) fp16 split hi (lda = K)
__device__ __half g_alo[NPAD * RANK];    // Agg(h) fp16 split lo
__device__ __half g_wh [RANK * RANK];    // (scale-folded) W^T fp16  [n][k]
__device__ float g_woff[3 * RANK];       // rank-1 BN offset per layer
__device__ float g_rho [NN];
__device__ float g_rhop[NN];
__device__ int   g_cnt   [NN];
__device__ int   g_cursor[NN];
__device__ int   g_rowptr[NN + 1];
__device__ float g_dinv  [NN];
__device__ int   g_esrc[EE];
__device__ float g_ew  [EE];
__device__ int   g_gptr[GG + 1];
__device__ float g_sum  [3 * RANK];      // per-layer BN stats
__device__ float g_sumsq[3 * RANK];
__device__ int   g_part[128];

// ---------------- BN param helper (recomputed locally, no bnfinal kernel) ---
__device__ __forceinline__ void bn_params(int layer, int c,
                                          const float* gamma, const float* beta,
                                          float& sc, float& sh) {
    float mu  = g_sum[layer * RANK + c]   * (1.0f / NN);
    float var = g_sumsq[layer * RANK + c] * (1.0f / NN) - mu * mu;
    sc = gamma[c] * rsqrtf(var + 1e-5f);
    sh = beta[c] - mu * sc;
}

// ---------------- graph preprocessing (once per call) -----------------------
__global__ void k_init() {
    int i = blockIdx.x * blockDim.x + threadIdx.x;
    if (i < NN) { g_cnt[i] = 0; g_cursor[i] = 0; g_rhop[i] = 0.f; }
    if (i < 3 * RANK) { g_sum[i] = 0.f; g_sumsq[i] = 0.f; g_woff[i] = 0.f; }
}

__global__ void k_hist(const int* __restrict__ dst) {
    int e = blockIdx.x * blockDim.x + threadIdx.x;
    if (e < EE) atomicAdd(&g_cnt[dst[e]], 1);
}

// dinv + scan phase 1 (block sums)
__global__ void k_dinvscan1() {
    __shared__ int sm[256];
    int b = blockIdx.x, t = threadIdx.x;
    if (b == 0 && t == 0) g_rowptr[NN] = EE;
    int base = b * 1024 + t * 4;
    int s = 0;
    #pragma unroll
    for (int j = 0; j < 4; j++) {
        int i = base + j;
        if (i < NN) {
            int c = g_cnt[i];
            s += c;
            g_dinv[i] = rsqrtf((float)(c + 1));
        }
    }
    sm[t] = s; __syncthreads();
    for (int off = 128; off > 0; off >>= 1) {
        if (t < off) sm[t] += sm[t + off];
        __syncthreads();
    }
    if (t == 0) g_part[b] = sm[0];
}

__global__ void k_scan2() {
    __shared__ int sm[128];
    int t = threadIdx.x;
    int v = (t < 98) ? g_part[t] : 0;
    sm[t] = v; __syncthreads();
    for (int off = 1; off < 128; off <<= 1) {
        int u = (t >= off) ? sm[t - off] : 0;
        __syncthreads();
        sm[t] += u;
        __syncthreads();
    }
    if (t < 98) g_part[t] = sm[t] - v;   // exclusive
}

// scan phase 3 (rowptr) + graph segment pointers
__global__ void k_scan3gptr(const int* __restrict__ batch) {
    __shared__ int sm[256];
    int b = blockIdx.x, t = threadIdx.x;
    int base = b * 1024 + t * 4;
    int v[4]; int s = 0;
    #pragma unroll
    for (int j = 0; j < 4; j++) { int i = base + j; v[j] = (i < NN) ? g_cnt[i] : 0; s += v[j]; }
    sm[t] = s; __syncthreads();
    for (int off = 1; off < 256; off <<= 1) {
        int u = (t >= off) ? sm[t - off] : 0;
        __syncthreads();
        sm[t] += u;
        __syncthreads();
    }
    int off0 = g_part[b] + (sm[t] - s);
    int run = 0;
    #pragma unroll
    for (int j = 0; j < 4; j++) {
        int i = base + j;
        if (i < NN) {
            g_rowptr[i] = off0 + run;
            // gptr logic
            int bi = batch[i];
            if (i == 0) {
                for (int g = 0; g <= bi; g++) g_gptr[g] = 0;
            } else {
                int bp = batch[i - 1];
                for (int g = bp + 1; g <= bi; g++) g_gptr[g] = i;
            }
            if (i == NN - 1) {
                for (int g = bi + 1; g <= GG; g++) g_gptr[g] = NN;
            }
        }
        run += v[j];
    }
}

__global__ void k_scatter(const int* __restrict__ src, const int* __restrict__ dst) {
    int e = blockIdx.x * blockDim.x + threadIdx.x;
    if (e >= EE) return;
    int s = src[e], d = dst[e];
    int pos = g_rowptr[d] + atomicAdd(&g_cursor[d], 1);
    float ds = g_dinv[s];
    g_esrc[pos] = s;
    g_ew[pos]   = ds * g_dinv[d];
    atomicAdd(&g_rhop[d], ds);
}

// x fp32 -> fp16 + rho finalize
__global__ void k_convXrho(const float* __restrict__ x) {
    int i4 = blockIdx.x * blockDim.x + threadIdx.x;
    if (i4 < NN) {
        float di = g_dinv[i4];
        g_rho[i4] = di * (g_rhop[i4] + di);
    }
    if (i4 >= NN * DIN / 4) return;
    float4 v = ((const float4*)x)[i4];
    __half2 a = __floats2half2_rn(v.x, v.y);
    __half2 b = __floats2half2_rn(v.z, v.w);
    *(uint2*)(g_hf16 + (size_t)i4 * 4) = make_uint2(*(uint32_t*)&a, *(uint32_t*)&b);
}

// ---------------- W convert (+BN scale fold) + rank-1 offset ---------------
// grid: RANK*K/256 conv blocks, plus (layer>0) 32 offset blocks.
__global__ void k_convWoff(const float* __restrict__ W, int K,
                           const float* __restrict__ gammaP,
                           const float* __restrict__ betaP, int layer) {
    int convB = RANK * K / 256;
    if ((int)blockIdx.x < convB) {
        int i = blockIdx.x * 256 + threadIdx.x;
        int n = i / K, k = i - n * K;
        float v = W[(size_t)k * RANK + n];
        if (layer > 0) {
            float sc, sh;
            bn_params(layer - 1, k, gammaP, betaP, sc, sh);
            v *= sc;
        }
        g_wh[i] = __float2half_rn(v);
    } else {
        // offset blocks (layer > 0 only): woff[n] += sum_k shift_k * W[k][n]
        int b2 = blockIdx.x - convB;
        int n = threadIdx.x;
        int kpb = K / 32;
        int k0 = b2 * kpb;
        float o = 0.f;
        for (int k = k0; k < k0 + kpb; k++) {
            float sc, sh;
            bn_params(layer - 1, k, gammaP, betaP, sc, sh);
            o = fmaf(sh, W[(size_t)k * RANK + n], o);
        }
        atomicAdd(&g_woff[layer * RANK + n], o);
    }
}

// ---------------- aggregation of fp16 h -> fp16 hi/lo split -----------------
#define ANPB 16
__global__ void __launch_bounds__(256)
k_aggH(int K) {
    int ncg  = K >> 3;
    int tid  = threadIdx.x;
    int cg   = (tid & (ncg - 1)) * 8;
    int sub  = tid / ncg;
    int nsub = 256 / ncg;
    int v0   = blockIdx.x * ANPB;

    for (int n = sub; n < ANPB; n += nsub) {
        int v = v0 + n;
        if (v >= NN) break;
        int beg = g_rowptr[v], end = g_rowptr[v + 1];
        float di = g_dinv[v];
        float w0 = di * di;

        float acc[8];
        {
            uint4 u = *(const uint4*)(g_hf16 + (size_t)v * K + cg);
            const __half2* hp = (const __half2*)&u;
            #pragma unroll
            for (int j = 0; j < 4; j++) {
                float2 f = __half22float2(hp[j]);
                acc[2 * j]     = w0 * f.x;
                acc[2 * j + 1] = w0 * f.y;
            }
        }
        int e = beg;
        for (; e + 2 <= end; e += 2) {
            float w1 = g_ew[e], w2 = g_ew[e + 1];
            int   s1 = g_esrc[e], s2 = g_esrc[e + 1];
            uint4 u1 = *(const uint4*)(g_hf16 + (size_t)s1 * K + cg);
            uint4 u2 = *(const uint4*)(g_hf16 + (size_t)s2 * K + cg);
            const __half2* h1 = (const __half2*)&u1;
            const __half2* h2 = (const __half2*)&u2;
            #pragma unroll
            for (int j = 0; j < 4; j++) {
                float2 f1 = __half22float2(h1[j]);
                float2 f2 = __half22float2(h2[j]);
                acc[2 * j]     = fmaf(w1, f1.x, acc[2 * j]);
                acc[2 * j + 1] = fmaf(w1, f1.y, acc[2 * j + 1]);
                acc[2 * j]     = fmaf(w2, f2.x, acc[2 * j]);
                acc[2 * j + 1] = fmaf(w2, f2.y, acc[2 * j + 1]);
            }
        }
        for (; e < end; e++) {
            float w = g_ew[e];
            int   s = g_esrc[e];
            uint4 u = *(const uint4*)(g_hf16 + (size_t)s * K + cg);
            const __half2* hp = (const __half2*)&u;
            #pragma unroll
            for (int j = 0; j < 4; j++) {
                float2 f = __half22float2(hp[j]);
                acc[2 * j]     = fmaf(w, f.x, acc[2 * j]);
                acc[2 * j + 1] = fmaf(w, f.y, acc[2 * j + 1]);
            }
        }

        __align__(16) __half hi[8], lo[8];
        #pragma unroll
        for (int j = 0; j < 8; j++) {
            hi[j] = __float2half_rn(acc[j]);
            lo[j] = __float2half_rn(acc[j] - __half2float(hi[j]));
        }
        *(uint4*)(g_ahi + (size_t)v * K + cg) = *(uint4*)hi;
        *(uint4*)(g_alo + (size_t)v * K + cg) = *(uint4*)lo;
    }
}

// ---------------- mma.sync fp16 2-term GEMM + fused tanh/BN-stat epilogue ---
// CTA 128(M) x 128(N), 256 threads (8 warps 2x4), warp 64x32, K chunk 64.
// D = (Ahi + Alo) @ Wfp16^T  (fp32 accum; exact in A, fp16-rounded W)
#define ASTRIDE 72
#define SA_ELEM (128 * ASTRIDE)
#define SB_ELEM (128 * ASTRIDE)
#define BUF_BYTES ((2 * SA_ELEM + SB_ELEM) * 2)     // 55296
#define GEMM_SMEM (2 * BUF_BYTES)                    // 110592

#define CP16(dst, src) do {                                                \
    uint32_t _d = (uint32_t)__cvta_generic_to_shared(dst);                 \
    asm volatile("cp.async.cg.shared.global [%0], [%1], 16;"               \
                 :: "r"(_d), "l"(src));                                    \
} while (0)

#define MMA16816(C, A, B) \
    asm volatile("mma.sync.aligned.m16n8k16.row.col.f32.f16.f16.f32 " \
        "{%0,%1,%2,%3}, {%4,%5,%6,%7}, {%8,%9}, {%0,%1,%2,%3};" \
        : "+f"((C)[0]), "+f"((C)[1]), "+f"((C)[2]), "+f"((C)[3]) \
        : "r"((A)[0]), "r"((A)[1]), "r"((A)[2]), "r"((A)[3]), \
          "r"((B)[0]), "r"((B)[1]))

__global__ void __launch_bounds__(256, 2)
k_gemm_mma(int K, const float* __restrict__ bias, int layer) {
    extern __shared__ __align__(16) char smem[];

    int tid = threadIdx.x;
    int wid = tid >> 5, lid = tid & 31;
    int m0  = blockIdx.x * 128;
    int n0  = blockIdx.y * 128;
    int wm  = (wid & 1) * 64;
    int wn  = (wid >> 1) * 32;
    int lr  = lid >> 2;
    int lc  = lid & 3;

    float c[4][4][4];
    #pragma unroll
    for (int i = 0; i < 4; i++)
        #pragma unroll
        for (int j = 0; j < 4; j++)
            #pragma unroll
            for (int q = 0; q < 4; q++) c[i][j][q] = 0.f;

    auto load_chunk = [&](int kc, char* base) {
        __half* sAh = (__half*)base;
        __half* sAl = sAh + SA_ELEM;
        __half* sB  = sAl + SA_ELEM;
        #pragma unroll
        for (int j = 0; j < 4; j++) {
            int i = tid * 4 + j;
            int r = i >> 3, kg = i & 7;
            size_t go = (size_t)(m0 + r) * K + kc + kg * 8;
            CP16(sAh + r * ASTRIDE + kg * 8, g_ahi + go);
            CP16(sAl + r * ASTRIDE + kg * 8, g_alo + go);
            size_t gob = (size_t)(n0 + r) * K + kc + kg * 8;
            CP16(sB + r * ASTRIDE + kg * 8, g_wh + gob);
        }
        asm volatile("cp.async.commit_group;" ::: "memory");
    };

    int nch = K >> 6;
    load_chunk(0, smem);

    for (int kc = 0; kc < nch; kc++) {
        if (kc + 1 < nch) {
            load_chunk((kc + 1) << 6, smem + ((kc + 1) & 1) * BUF_BYTES);
            asm volatile("cp.async.wait_group 1;" ::: "memory");
        } else {
            asm volatile("cp.async.wait_group 0;" ::: "memory");
        }
        __syncthreads();

        char* base = smem + (kc & 1) * BUF_BYTES;
        __half* sAh = (__half*)base;
        __half* sAl = sAh + SA_ELEM;
        __half* sB  = sAl + SA_ELEM;

        #pragma unroll
        for (int ks = 0; ks < 4; ks++) {
            int koff = ks * 16 + lc * 2;
            uint32_t bb[4][2];
            #pragma unroll
            for (int fn = 0; fn < 4; fn++) {
                int n = wn + fn * 8 + lr;
                bb[fn][0] = *(const uint32_t*)(sB + n * ASTRIDE + koff);
                bb[fn][1] = *(const uint32_t*)(sB + n * ASTRIDE + koff + 8);
            }
            #pragma unroll
            for (int fm = 0; fm < 4; fm++) {
                int m = wm + fm * 16 + lr;
                uint32_t ah[4], al[4];
                ah[0] = *(const uint32_t*)(sAh + m * ASTRIDE + koff);
                ah[1] = *(const uint32_t*)(sAh + (m + 8) * ASTRIDE + koff);
                ah[2] = *(const uint32_t*)(sAh + m * ASTRIDE + koff + 8);
                ah[3] = *(const uint32_t*)(sAh + (m + 8) * ASTRIDE + koff + 8);
                al[0] = *(const uint32_t*)(sAl + m * ASTRIDE + koff);
                al[1] = *(const uint32_t*)(sAl + (m + 8) * ASTRIDE + koff);
                al[2] = *(const uint32_t*)(sAl + m * ASTRIDE + koff + 8);
                al[3] = *(const uint32_t*)(sAl + (m + 8) * ASTRIDE + koff + 8);
                #pragma unroll
                for (int fn = 0; fn < 4; fn++) {
                    MMA16816(c[fm][fn], ah, bb[fn]);
                    MMA16816(c[fm][fn], al, bb[fn]);
                }
            }
        }
        __syncthreads();
    }

    // ---- fused epilogue: y = acc + rho*woff + bias; h = tanh(y) ----
    const float* woff = g_woff + layer * RANK;
    float woffv[8], biasv[8];
    #pragma unroll
    for (int fn = 0; fn < 4; fn++) {
        int col = n0 + wn + fn * 8 + lc * 2;
        woffv[fn * 2]     = woff[col];
        woffv[fn * 2 + 1] = woff[col + 1];
        biasv[fn * 2]     = bias[col];
        biasv[fn * 2 + 1] = bias[col + 1];
    }

    float ts[8], tq[8];
    #pragma unroll
    for (int j = 0; j < 8; j++) { ts[j] = 0.f; tq[j] = 0.f; }

    #pragma unroll
    for (int fm = 0; fm < 4; fm++) {
        int r0 = m0 + wm + fm * 16 + lr;
        int r1 = r0 + 8;
        float rho0 = (r0 < NN) ? g_rho[r0] : 0.f;
        float rho1 = (r1 < NN) ? g_rho[r1] : 0.f;
        #pragma unroll
        for (int fn = 0; fn < 4; fn++) {
            int col = n0 + wn + fn * 8 + lc * 2;
            float w0v = woffv[fn * 2], w1v = woffv[fn * 2 + 1];
            float b0v = biasv[fn * 2], b1v = biasv[fn * 2 + 1];
            if (r0 < NN) {
                float h00 = tanhf(c[fm][fn][0] + rho0 * w0v + b0v);
                float h01 = tanhf(c[fm][fn][1] + rho0 * w1v + b1v);
                *(__half2*)(g_hf16 + (size_t)r0 * RANK + col) = __floats2half2_rn(h00, h01);
                ts[fn * 2] += h00;     tq[fn * 2]     = fmaf(h00, h00, tq[fn * 2]);
                ts[fn * 2 + 1] += h01; tq[fn * 2 + 1] = fmaf(h01, h01, tq[fn * 2 + 1]);
            }
            if (r1 < NN) {
                float h10 = tanhf(c[fm][fn][2] + rho1 * w0v + b0v);
                float h11 = tanhf(c[fm][fn][3] + rho1 * w1v + b1v);
                *(__half2*)(g_hf16 + (size_t)r1 * RANK + col) = __floats2half2_rn(h10, h11);
                ts[fn * 2] += h10;     tq[fn * 2]     = fmaf(h10, h10, tq[fn * 2]);
                ts[fn * 2 + 1] += h11; tq[fn * 2 + 1] = fmaf(h11, h11, tq[fn * 2 + 1]);
            }
        }
    }

    // warp reduce over lr (lanes differing in bits 2..4)
    #pragma unroll
    for (int off = 4; off < 32; off <<= 1) {
        #pragma unroll
        for (int j = 0; j < 8; j++) {
            ts[j] += __shfl_xor_sync(0xffffffff, ts[j], off);
            tq[j] += __shfl_xor_sync(0xffffffff, tq[j], off);
        }
    }

    float* red = (float*)smem;   // [0:128) sum, [128:256) sq, for cols n0..n0+127
    __syncthreads();
    if (tid < 128) { red[tid] = 0.f; red[128 + tid] = 0.f; }
    __syncthreads();
    if (lr == 0) {
        #pragma unroll
        for (int fn = 0; fn < 4; fn++) {
            int lcol = wn + fn * 8 + lc * 2;
            atomicAdd(&red[lcol],           ts[fn * 2]);
            atomicAdd(&red[lcol + 1],       ts[fn * 2 + 1]);
            atomicAdd(&red[128 + lcol],     tq[fn * 2]);
            atomicAdd(&red[128 + lcol + 1], tq[fn * 2 + 1]);
        }
    }
    __syncthreads();
    if (tid < 128) {
        atomicAdd(&g_sum[layer * RANK + n0 + tid],   red[tid]);
        atomicAdd(&g_sumsq[layer * RANK + n0 + tid], red[128 + tid]);
    }
}

// ---------------- pool (BN applied on the fly) -------------------------------
__global__ void k_pool(float* __restrict__ out,
                       const float* __restrict__ gamma,
                       const float* __restrict__ beta, int layer) {
    int g = blockIdx.x, c = threadIdx.x;
    int beg = g_gptr[g], end = g_gptr[g + 1];
    float sc, sh;
    bn_params(layer, c, gamma, beta, sc, sh);
    float m = -INFINITY;
    for (int r = beg; r < end; r++) {
        float h = __half2float(g_hf16[(size_t)r * RANK + c]);
        m = fmaxf(m, fmaf(sc, h, sh));
    }
    out[(size_t)g * RANK + c] = (end > beg) ? m : 0.0f;
}

// ---------------- launch ----------------------------------------------------
extern "C" void kernel_launch(void* const* d_in, const int* in_sizes, int n_in,
                              void* d_out, int out_size) {
    const float* x     = (const float*)d_in[0];
    const int*   ei    = (const int*)  d_in[1];   // [2, E] int32
    const int*   batch = (const int*)  d_in[2];
    const float* W[3]     = { (const float*)d_in[3],  (const float*)d_in[7],  (const float*)d_in[11] };
    const float* b[3]     = { (const float*)d_in[4],  (const float*)d_in[8],  (const float*)d_in[12] };
    const float* gamma[3] = { (const float*)d_in[5],  (const float*)d_in[9],  (const float*)d_in[13] };
    const float* beta[3]  = { (const float*)d_in[6],  (const float*)d_in[10], (const float*)d_in[14] };
    const int* src = ei;
    const int* dst = ei + EE;
    float* out = (float*)d_out;

    cudaFuncSetAttribute(k_gemm_mma, cudaFuncAttributeMaxDynamicSharedMemorySize, GEMM_SMEM);

    k_init     <<<(NN + 255) / 256, 256>>>();
    k_hist     <<<(EE + 255) / 256, 256>>>(dst);
    k_dinvscan1<<<98, 256>>>();
    k_scan2    <<<1, 128>>>();
    k_scan3gptr<<<98, 256>>>(batch);
    k_scatter  <<<(EE + 255) / 256, 256>>>(src, dst);
    k_convXrho <<<(NN * DIN / 4 + 255) / 256, 256>>>(x);

    dim3 gemm_grid((NN + 127) / 128, 2);   // 782 x 2
    int ablocks = (NN + ANPB - 1) / ANPB;
    for (int l = 0; l < 3; l++) {
        int K = (l == 0) ? DIN : RANK;
        int convB = RANK * K / 256;
        int wBlocks = convB + ((l > 0) ? 32 : 0);
        k_convWoff<<<wBlocks, 256>>>(W[l], K, (l > 0) ? gamma[l - 1] : gamma[0],
                                     (l > 0) ? beta[l - 1] : beta[0], l);
        k_aggH<<<ablocks, 256>>>(K);
        k_gemm_mma<<<gemm_grid, 256, GEMM_SMEM>>>(K, b[l], l);
        k_pool<<<GG, RANK>>>(out + (size_t)l * GG * RANK, gamma[l], beta[l], l);
    }
}

// round 10
// speedup vs baseline: 3.5231x; 1.2876x over previous
#include <cuda_runtime.h>
#include <cuda_fp16.h>
#include <math.h>
#include <stdint.h>

#define NN   100000
#define NPAD 100096          // 782 * 128
#define EE   400000
#define GG   2048
#define DIN  128
#define RANK 256

// ---------------- scratch (device globals: no allocations allowed) ----------
__device__ __half g_hf16[NPAD * RANK];   // h (tanh out) fp16; also x fp16 (lda=K)
__device__ __half g_ah [NPAD * RANK];    // Agg(h) fp16 (lda = K)
__device__ __half g_wh [RANK * RANK];    // (scale-folded) W^T fp16  [n][k]
__device__ float g_woff[3 * RANK];       // rank-1 BN offset per layer
__device__ float g_rho [NN];
__device__ float g_rhop[NN];
__device__ int   g_cnt   [NN];
__device__ int   g_cursor[NN];
__device__ int   g_rowptr[NN + 1];
__device__ float g_dinv  [NN];
__device__ int   g_esrc[EE];
__device__ float g_ew  [EE];
__device__ int   g_gptr[GG + 1];
__device__ float g_sum  [3 * RANK];      // per-layer BN stats
__device__ float g_sumsq[3 * RANK];
__device__ int   g_part[128];

// ---------------- BN param helper -------------------------------------------
__device__ __forceinline__ void bn_params(int layer, int c,
                                          const float* gamma, const float* beta,
                                          float& sc, float& sh) {
    float mu  = g_sum[layer * RANK + c]   * (1.0f / NN);
    float var = g_sumsq[layer * RANK + c] * (1.0f / NN) - mu * mu;
    sc = gamma[c] * rsqrtf(var + 1e-5f);
    sh = beta[c] - mu * sc;
}

// ---------------- graph preprocessing (once per call) -----------------------
__global__ void k_init() {
    int i = blockIdx.x * blockDim.x + threadIdx.x;
    if (i < NN) { g_cnt[i] = 0; g_cursor[i] = 0; g_rhop[i] = 0.f; }
    if (i < 3 * RANK) { g_sum[i] = 0.f; g_sumsq[i] = 0.f; g_woff[i] = 0.f; }
}

__global__ void k_hist(const int* __restrict__ dst) {
    int e = blockIdx.x * blockDim.x + threadIdx.x;
    if (e < EE) atomicAdd(&g_cnt[dst[e]], 1);
}

// dinv + scan phase 1 (block sums)
__global__ void k_dinvscan1() {
    __shared__ int sm[256];
    int b = blockIdx.x, t = threadIdx.x;
    if (b == 0 && t == 0) g_rowptr[NN] = EE;
    int base = b * 1024 + t * 4;
    int s = 0;
    #pragma unroll
    for (int j = 0; j < 4; j++) {
        int i = base + j;
        if (i < NN) {
            int c = g_cnt[i];
            s += c;
            g_dinv[i] = rsqrtf((float)(c + 1));
        }
    }
    sm[t] = s; __syncthreads();
    for (int off = 128; off > 0; off >>= 1) {
        if (t < off) sm[t] += sm[t + off];
        __syncthreads();
    }
    if (t == 0) g_part[b] = sm[0];
}

__global__ void k_scan2() {
    __shared__ int sm[128];
    int t = threadIdx.x;
    int v = (t < 98) ? g_part[t] : 0;
    sm[t] = v; __syncthreads();
    for (int off = 1; off < 128; off <<= 1) {
        int u = (t >= off) ? sm[t - off] : 0;
        __syncthreads();
        sm[t] += u;
        __syncthreads();
    }
    if (t < 98) g_part[t] = sm[t] - v;   // exclusive
}

// scan phase 3 (rowptr) + graph segment pointers
__global__ void k_scan3gptr(const int* __restrict__ batch) {
    __shared__ int sm[256];
    int b = blockIdx.x, t = threadIdx.x;
    int base = b * 1024 + t * 4;
    int v[4]; int s = 0;
    #pragma unroll
    for (int j = 0; j < 4; j++) { int i = base + j; v[j] = (i < NN) ? g_cnt[i] : 0; s += v[j]; }
    sm[t] = s; __syncthreads();
    for (int off = 1; off < 256; off <<= 1) {
        int u = (t >= off) ? sm[t - off] : 0;
        __syncthreads();
        sm[t] += u;
        __syncthreads();
    }
    int off0 = g_part[b] + (sm[t] - s);
    int run = 0;
    #pragma unroll
    for (int j = 0; j < 4; j++) {
        int i = base + j;
        if (i < NN) {
            g_rowptr[i] = off0 + run;
            int bi = batch[i];
            if (i == 0) {
                for (int g = 0; g <= bi; g++) g_gptr[g] = 0;
            } else {
                int bp = batch[i - 1];
                for (int g = bp + 1; g <= bi; g++) g_gptr[g] = i;
            }
            if (i == NN - 1) {
                for (int g = bi + 1; g <= GG; g++) g_gptr[g] = NN;
            }
        }
        run += v[j];
    }
}

__global__ void k_scatter(const int* __restrict__ src, const int* __restrict__ dst) {
    int e = blockIdx.x * blockDim.x + threadIdx.x;
    if (e >= EE) return;
    int s = src[e], d = dst[e];
    int pos = g_rowptr[d] + atomicAdd(&g_cursor[d], 1);
    float ds = g_dinv[s];
    g_esrc[pos] = s;
    g_ew[pos]   = ds * g_dinv[d];
    atomicAdd(&g_rhop[d], ds);
}

// x fp32 -> fp16 + rho finalize
__global__ void k_convXrho(const float* __restrict__ x) {
    int i4 = blockIdx.x * blockDim.x + threadIdx.x;
    if (i4 < NN) {
        float di = g_dinv[i4];
        g_rho[i4] = di * (g_rhop[i4] + di);
    }
    if (i4 >= NN * DIN / 4) return;
    float4 v = ((const float4*)x)[i4];
    __half2 a = __floats2half2_rn(v.x, v.y);
    __half2 b = __floats2half2_rn(v.z, v.w);
    *(uint2*)(g_hf16 + (size_t)i4 * 4) = make_uint2(*(uint32_t*)&a, *(uint32_t*)&b);
}

// ---------------- W convert (+BN scale fold) + rank-1 offset ---------------
__global__ void k_convWoff(const float* __restrict__ W, int K,
                           const float* __restrict__ gammaP,
                           const float* __restrict__ betaP, int layer) {
    int convB = RANK * K / 256;
    if ((int)blockIdx.x < convB) {
        int i = blockIdx.x * 256 + threadIdx.x;
        int n = i / K, k = i - n * K;
        float v = W[(size_t)k * RANK + n];
        if (layer > 0) {
            float sc, sh;
            bn_params(layer - 1, k, gammaP, betaP, sc, sh);
            v *= sc;
        }
        g_wh[i] = __float2half_rn(v);
    } else {
        int b2 = blockIdx.x - convB;
        int n = threadIdx.x;
        int kpb = K / 32;
        int k0 = b2 * kpb;
        float o = 0.f;
        for (int k = k0; k < k0 + kpb; k++) {
            float sc, sh;
            bn_params(layer - 1, k, gammaP, betaP, sc, sh);
            o = fmaf(sh, W[(size_t)k * RANK + n], o);
        }
        atomicAdd(&g_woff[layer * RANK + n], o);
    }
}

// ---------------- aggregation of fp16 h -> fp16 ------------------------------
#define ANPB 16
__global__ void __launch_bounds__(256)
k_aggH(int K) {
    int ncg  = K >> 3;
    int tid  = threadIdx.x;
    int cg   = (tid & (ncg - 1)) * 8;
    int sub  = tid / ncg;
    int nsub = 256 / ncg;
    int v0   = blockIdx.x * ANPB;

    for (int n = sub; n < ANPB; n += nsub) {
        int v = v0 + n;
        if (v >= NN) break;
        int beg = g_rowptr[v], end = g_rowptr[v + 1];
        float di = g_dinv[v];
        float w0 = di * di;

        float acc[8];
        {
            uint4 u = *(const uint4*)(g_hf16 + (size_t)v * K + cg);
            const __half2* hp = (const __half2*)&u;
            #pragma unroll
            for (int j = 0; j < 4; j++) {
                float2 f = __half22float2(hp[j]);
                acc[2 * j]     = w0 * f.x;
                acc[2 * j + 1] = w0 * f.y;
            }
        }
        int e = beg;
        for (; e + 2 <= end; e += 2) {
            float w1 = g_ew[e], w2 = g_ew[e + 1];
            int   s1 = g_esrc[e], s2 = g_esrc[e + 1];
            uint4 u1 = *(const uint4*)(g_hf16 + (size_t)s1 * K + cg);
            uint4 u2 = *(const uint4*)(g_hf16 + (size_t)s2 * K + cg);
            const __half2* h1 = (const __half2*)&u1;
            const __half2* h2 = (const __half2*)&u2;
            #pragma unroll
            for (int j = 0; j < 4; j++) {
                float2 f1 = __half22float2(h1[j]);
                float2 f2 = __half22float2(h2[j]);
                acc[2 * j]     = fmaf(w1, f1.x, acc[2 * j]);
                acc[2 * j + 1] = fmaf(w1, f1.y, acc[2 * j + 1]);
                acc[2 * j]     = fmaf(w2, f2.x, acc[2 * j]);
                acc[2 * j + 1] = fmaf(w2, f2.y, acc[2 * j + 1]);
            }
        }
        for (; e < end; e++) {
            float w = g_ew[e];
            int   s = g_esrc[e];
            uint4 u = *(const uint4*)(g_hf16 + (size_t)s * K + cg);
            const __half2* hp = (const __half2*)&u;
            #pragma unroll
            for (int j = 0; j < 4; j++) {
                float2 f = __half22float2(hp[j]);
                acc[2 * j]     = fmaf(w, f.x, acc[2 * j]);
                acc[2 * j + 1] = fmaf(w, f.y, acc[2 * j + 1]);
            }
        }

        __align__(16) __half o[8];
        #pragma unroll
        for (int j = 0; j < 8; j++) o[j] = __float2half_rn(acc[j]);
        *(uint4*)(g_ah + (size_t)v * K + cg) = *(uint4*)o;
    }
}

// ---------------- mma.sync fp16 GEMM + fused tanh/BN-stat epilogue ----------
// CTA 128(M) x 128(N), 256 threads (8 warps 2x4), warp 64x32, K chunk 64.
#define ASTRIDE 72
#define SA_ELEM (128 * ASTRIDE)
#define SB_ELEM (128 * ASTRIDE)
#define BUF_BYTES ((SA_ELEM + SB_ELEM) * 2)     // 36864
#define GEMM_SMEM (2 * BUF_BYTES)                // 73728

#define CP16(dst, src) do {                                                \
    uint32_t _d = (uint32_t)__cvta_generic_to_shared(dst);                 \
    asm volatile("cp.async.cg.shared.global [%0], [%1], 16;"               \
                 :: "r"(_d), "l"(src));                                    \
} while (0)

#define MMA16816(C, A, B) \
    asm volatile("mma.sync.aligned.m16n8k16.row.col.f32.f16.f16.f32 " \
        "{%0,%1,%2,%3}, {%4,%5,%6,%7}, {%8,%9}, {%0,%1,%2,%3};" \
        : "+f"((C)[0]), "+f"((C)[1]), "+f"((C)[2]), "+f"((C)[3]) \
        : "r"((A)[0]), "r"((A)[1]), "r"((A)[2]), "r"((A)[3]), \
          "r"((B)[0]), "r"((B)[1]))

__global__ void __launch_bounds__(256, 2)
k_gemm_mma(int K, const float* __restrict__ bias, int layer) {
    extern __shared__ __align__(16) char smem[];

    int tid = threadIdx.x;
    int wid = tid >> 5, lid = tid & 31;
    int m0  = blockIdx.x * 128;
    int n0  = blockIdx.y * 128;
    int wm  = (wid & 1) * 64;
    int wn  = (wid >> 1) * 32;
    int lr  = lid >> 2;
    int lc  = lid & 3;

    float c[4][4][4];
    #pragma unroll
    for (int i = 0; i < 4; i++)
        #pragma unroll
        for (int j = 0; j < 4; j++)
            #pragma unroll
            for (int q = 0; q < 4; q++) c[i][j][q] = 0.f;

    auto load_chunk = [&](int kc, char* base) {
        __half* sA = (__half*)base;
        __half* sB = sA + SA_ELEM;
        #pragma unroll
        for (int j = 0; j < 4; j++) {
            int i = tid * 4 + j;
            int r = i >> 3, kg = i & 7;
            size_t go = (size_t)(m0 + r) * K + kc + kg * 8;
            CP16(sA + r * ASTRIDE + kg * 8, g_ah + go);
            size_t gob = (size_t)(n0 + r) * K + kc + kg * 8;
            CP16(sB + r * ASTRIDE + kg * 8, g_wh + gob);
        }
        asm volatile("cp.async.commit_group;" ::: "memory");
    };

    int nch = K >> 6;
    load_chunk(0, smem);

    for (int kc = 0; kc < nch; kc++) {
        if (kc + 1 < nch) {
            load_chunk((kc + 1) << 6, smem + ((kc + 1) & 1) * BUF_BYTES);
            asm volatile("cp.async.wait_group 1;" ::: "memory");
        } else {
            asm volatile("cp.async.wait_group 0;" ::: "memory");
        }
        __syncthreads();

        char* base = smem + (kc & 1) * BUF_BYTES;
        __half* sA = (__half*)base;
        __half* sB = sA + SA_ELEM;

        #pragma unroll
        for (int ks = 0; ks < 4; ks++) {
            int koff = ks * 16 + lc * 2;
            uint32_t bb[4][2];
            #pragma unroll
            for (int fn = 0; fn < 4; fn++) {
                int n = wn + fn * 8 + lr;
                bb[fn][0] = *(const uint32_t*)(sB + n * ASTRIDE + koff);
                bb[fn][1] = *(const uint32_t*)(sB + n * ASTRIDE + koff + 8);
            }
            #pragma unroll
            for (int fm = 0; fm < 4; fm++) {
                int m = wm + fm * 16 + lr;
                uint32_t aa[4];
                aa[0] = *(const uint32_t*)(sA + m * ASTRIDE + koff);
                aa[1] = *(const uint32_t*)(sA + (m + 8) * ASTRIDE + koff);
                aa[2] = *(const uint32_t*)(sA + m * ASTRIDE + koff + 8);
                aa[3] = *(const uint32_t*)(sA + (m + 8) * ASTRIDE + koff + 8);
                #pragma unroll
                for (int fn = 0; fn < 4; fn++)
                    MMA16816(c[fm][fn], aa, bb[fn]);
            }
        }
        __syncthreads();
    }

    // ---- fused epilogue: y = acc + rho*woff + bias; h = tanh(y) ----
    const float* woff = g_woff + layer * RANK;
    float woffv[8], biasv[8];
    #pragma unroll
    for (int fn = 0; fn < 4; fn++) {
        int col = n0 + wn + fn * 8 + lc * 2;
        woffv[fn * 2]     = woff[col];
        woffv[fn * 2 + 1] = woff[col + 1];
        biasv[fn * 2]     = bias[col];
        biasv[fn * 2 + 1] = bias[col + 1];
    }

    float ts[8], tq[8];
    #pragma unroll
    for (int j = 0; j < 8; j++) { ts[j] = 0.f; tq[j] = 0.f; }

    #pragma unroll
    for (int fm = 0; fm < 4; fm++) {
        int r0 = m0 + wm + fm * 16 + lr;
        int r1 = r0 + 8;
        float rho0 = (r0 < NN) ? g_rho[r0] : 0.f;
        float rho1 = (r1 < NN) ? g_rho[r1] : 0.f;
        #pragma unroll
        for (int fn = 0; fn < 4; fn++) {
            int col = n0 + wn + fn * 8 + lc * 2;
            float w0v = woffv[fn * 2], w1v = woffv[fn * 2 + 1];
            float b0v = biasv[fn * 2], b1v = biasv[fn * 2 + 1];
            if (r0 < NN) {
                float h00 = tanhf(c[fm][fn][0] + rho0 * w0v + b0v);
                float h01 = tanhf(c[fm][fn][1] + rho0 * w1v + b1v);
                *(__half2*)(g_hf16 + (size_t)r0 * RANK + col) = __floats2half2_rn(h00, h01);
                ts[fn * 2] += h00;     tq[fn * 2]     = fmaf(h00, h00, tq[fn * 2]);
                ts[fn * 2 + 1] += h01; tq[fn * 2 + 1] = fmaf(h01, h01, tq[fn * 2 + 1]);
            }
            if (r1 < NN) {
                float h10 = tanhf(c[fm][fn][2] + rho1 * w0v + b0v);
                float h11 = tanhf(c[fm][fn][3] + rho1 * w1v + b1v);
                *(__half2*)(g_hf16 + (size_t)r1 * RANK + col) = __floats2half2_rn(h10, h11);
                ts[fn * 2] += h10;     tq[fn * 2]     = fmaf(h10, h10, tq[fn * 2]);
                ts[fn * 2 + 1] += h11; tq[fn * 2 + 1] = fmaf(h11, h11, tq[fn * 2 + 1]);
            }
        }
    }

    #pragma unroll
    for (int off = 4; off < 32; off <<= 1) {
        #pragma unroll
        for (int j = 0; j < 8; j++) {
            ts[j] += __shfl_xor_sync(0xffffffff, ts[j], off);
            tq[j] += __shfl_xor_sync(0xffffffff, tq[j], off);
        }
    }

    float* red = (float*)smem;   // [0:128) sum, [128:256) sq
    __syncthreads();
    if (tid < 128) { red[tid] = 0.f; red[128 + tid] = 0.f; }
    __syncthreads();
    if (lr == 0) {
        #pragma unroll
        for (int fn = 0; fn < 4; fn++) {
            int lcol = wn + fn * 8 + lc * 2;
            atomicAdd(&red[lcol],           ts[fn * 2]);
            atomicAdd(&red[lcol + 1],       ts[fn * 2 + 1]);
            atomicAdd(&red[128 + lcol],     tq[fn * 2]);
            atomicAdd(&red[128 + lcol + 1], tq[fn * 2 + 1]);
        }
    }
    __syncthreads();
    if (tid < 128) {
        atomicAdd(&g_sum[layer * RANK + n0 + tid],   red[tid]);
        atomicAdd(&g_sumsq[layer * RANK + n0 + tid], red[128 + tid]);
    }
}

// ---------------- pool (BN applied on the fly) -------------------------------
__global__ void k_pool(float* __restrict__ out,
                       const float* __restrict__ gamma,
                       const float* __restrict__ beta, int layer) {
    int g = blockIdx.x, c = threadIdx.x;
    int beg = g_gptr[g], end = g_gptr[g + 1];
    float sc, sh;
    bn_params(layer, c, gamma, beta, sc, sh);
    float m0 = -INFINITY, m1 = -INFINITY;
    int r = beg;
    for (; r + 2 <= end; r += 2) {
        float h0 = __half2float(g_hf16[(size_t)r * RANK + c]);
        float h1 = __half2float(g_hf16[(size_t)(r + 1) * RANK + c]);
        m0 = fmaxf(m0, h0);
        m1 = fmaxf(m1, h1);
    }
    if (r < end) m0 = fmaxf(m0, __half2float(g_hf16[(size_t)r * RANK + c]));
    float m = fmaxf(m0, m1);
    out[(size_t)g * RANK + c] = (end > beg) ? fmaf(sc, m * 0.f + m, 0.f) * 0.f + fmaf(sc, m, sh) : 0.0f;
}

// ---------------- launch ----------------------------------------------------
extern "C" void kernel_launch(void* const* d_in, const int* in_sizes, int n_in,
                              void* d_out, int out_size) {
    const float* x     = (const float*)d_in[0];
    const int*   ei    = (const int*)  d_in[1];   // [2, E] int32
    const int*   batch = (const int*)  d_in[2];
    const float* W[3]     = { (const float*)d_in[3],  (const float*)d_in[7],  (const float*)d_in[11] };
    const float* b[3]     = { (const float*)d_in[4],  (const float*)d_in[8],  (const float*)d_in[12] };
    const float* gamma[3] = { (const float*)d_in[5],  (const float*)d_in[9],  (const float*)d_in[13] };
    const float* beta[3]  = { (const float*)d_in[6],  (const float*)d_in[10], (const float*)d_in[14] };
    const int* src = ei;
    const int* dst = ei + EE;
    float* out = (float*)d_out;

    cudaFuncSetAttribute(k_gemm_mma, cudaFuncAttributeMaxDynamicSharedMemorySize, GEMM_SMEM);

    k_init     <<<(NN + 255) / 256, 256>>>();
    k_hist     <<<(EE + 255) / 256, 256>>>(dst);
    k_dinvscan1<<<98, 256>>>();
    k_scan2    <<<1, 128>>>();
    k_scan3gptr<<<98, 256>>>(batch);
    k_scatter  <<<(EE + 255) / 256, 256>>>(src, dst);
    k_convXrho <<<(NN * DIN / 4 + 255) / 256, 256>>>(x);

    dim3 gemm_grid((NN + 127) / 128, 2);   // 782 x 2
    int ablocks = (NN + ANPB - 1) / ANPB;
    for (int l = 0; l < 3; l++) {
        int K = (l == 0) ? DIN : RANK;
        int convB = RANK * K / 256;
        int wBlocks = convB + ((l > 0) ? 32 : 0);
        k_convWoff<<<wBlocks, 256>>>(W[l], K, (l > 0) ? gamma[l - 1] : gamma[0],
                                     (l > 0) ? beta[l - 1] : beta[0], l);
        k_aggH<<<ablocks, 256>>>(K);
        k_gemm_mma<<<gemm_grid, 256, GEMM_SMEM>>>(K, b[l], l);
        k_pool<<<GG, RANK>>>(out + (size_t)l * GG * RANK, gamma[l], beta[l], l);
    }
}

// round 11
// speedup vs baseline: 3.8180x; 1.0837x over previous
#include <cuda_runtime.h>
#include <cuda_fp16.h>
#include <math.h>
#include <stdint.h>

#define NN   100000
#define NPAD 100096          // 782 * 128
#define EE   400000
#define GG   2048
#define DIN  128
#define RANK 256

// ---------------- scratch (device globals: no allocations allowed) ----------
__device__ __half g_hf16[NPAD * RANK];   // h (tanh out) fp16; also x fp16 (lda=K)
__device__ __half g_ah [NPAD * RANK];    // Agg(h) fp16 (lda = K)
__device__ __half g_wh [RANK * RANK];    // (scale-folded) W^T fp16  [n][k]
__device__ float g_woff[3 * RANK];       // rank-1 BN offset per layer
__device__ float g_rhop[NN];
__device__ int   g_cnt   [NN];
__device__ int   g_cursor[NN];
__device__ int   g_rowptr[NN + 1];
__device__ float g_dinv  [NN];
__device__ int   g_esrc[EE];
__device__ float g_ew  [EE];
__device__ int   g_gptr[GG + 1];
__device__ float g_sum  [3 * RANK];      // per-layer BN stats
__device__ float g_sumsq[3 * RANK];
__device__ int   g_part[128];

// ---------------- BN param helper -------------------------------------------
__device__ __forceinline__ void bn_params(int layer, int c,
                                          const float* gamma, const float* beta,
                                          float& sc, float& sh) {
    float mu  = g_sum[layer * RANK + c]   * (1.0f / NN);
    float var = g_sumsq[layer * RANK + c] * (1.0f / NN) - mu * mu;
    sc = gamma[c] * rsqrtf(var + 1e-5f);
    sh = beta[c] - mu * sc;
}

// ---------------- graph preprocessing ----------------------------------------
__global__ void k_init() {
    int i = blockIdx.x * blockDim.x + threadIdx.x;
    if (i < NN) { g_cnt[i] = 0; g_cursor[i] = 0; g_rhop[i] = 0.f; }
    if (i < 3 * RANK) { g_sum[i] = 0.f; g_sumsq[i] = 0.f; g_woff[i] = 0.f; }
}

// hist + convW0 + x->fp16, one launch (independent block ranges)
#define HISTB 1563            // ceil(EE/256)
#define CONVW0B (RANK * DIN / 256)   // 128
#define CONVXB (NN * DIN / 4 / 256)  // 12500
__global__ void k_histconv(const int* __restrict__ dst,
                           const float* __restrict__ W0,
                           const float* __restrict__ x) {
    int b = blockIdx.x;
    if (b < HISTB) {
        int e = b * 256 + threadIdx.x;
        if (e < EE) atomicAdd(&g_cnt[dst[e]], 1);
    } else if (b < HISTB + CONVW0B) {
        int i = (b - HISTB) * 256 + threadIdx.x;     // over RANK*DIN
        int n = i / DIN, k = i - n * DIN;
        g_wh[i] = __float2half_rn(W0[(size_t)k * RANK + n]);
    } else {
        int i4 = (b - HISTB - CONVW0B) * 256 + threadIdx.x;
        if (i4 < NN * DIN / 4) {
            float4 v = ((const float4*)x)[i4];
            __half2 a = __floats2half2_rn(v.x, v.y);
            __half2 c = __floats2half2_rn(v.z, v.w);
            *(uint2*)(g_hf16 + (size_t)i4 * 4) = make_uint2(*(uint32_t*)&a, *(uint32_t*)&c);
        }
    }
}

// dinv + scan phase 1 (block sums)
__global__ void k_dinvscan1() {
    __shared__ int sm[256];
    int b = blockIdx.x, t = threadIdx.x;
    if (b == 0 && t == 0) g_rowptr[NN] = EE;
    int base = b * 1024 + t * 4;
    int s = 0;
    #pragma unroll
    for (int j = 0; j < 4; j++) {
        int i = base + j;
        if (i < NN) {
            int c = g_cnt[i];
            s += c;
            g_dinv[i] = rsqrtf((float)(c + 1));
        }
    }
    sm[t] = s; __syncthreads();
    for (int off = 128; off > 0; off >>= 1) {
        if (t < off) sm[t] += sm[t + off];
        __syncthreads();
    }
    if (t == 0) g_part[b] = sm[0];
}

// scan phase 2 (in-block re-scan of partials) + phase 3 + gptr
__global__ void k_scan3gptr(const int* __restrict__ batch) {
    __shared__ int sm[256];
    __shared__ int sp[128];
    int b = blockIdx.x, t = threadIdx.x;

    // in-block scan of the 98 block partials (replaces separate kernel)
    if (t < 128) sp[t] = (t < 98) ? g_part[t] : 0;
    __syncthreads();
    for (int off = 1; off < 128; off <<= 1) {
        int u = (t >= off && t < 128) ? sp[t - off] : 0;
        __syncthreads();
        if (t < 128) sp[t] += u;
        __syncthreads();
    }
    int blockPrefix = (b > 0) ? sp[b - 1] : 0;   // exclusive

    int base = b * 1024 + t * 4;
    int v[4]; int s = 0;
    #pragma unroll
    for (int j = 0; j < 4; j++) { int i = base + j; v[j] = (i < NN) ? g_cnt[i] : 0; s += v[j]; }
    sm[t] = s; __syncthreads();
    for (int off = 1; off < 256; off <<= 1) {
        int u = (t >= off) ? sm[t - off] : 0;
        __syncthreads();
        sm[t] += u;
        __syncthreads();
    }
    int off0 = blockPrefix + (sm[t] - s);
    int run = 0;
    #pragma unroll
    for (int j = 0; j < 4; j++) {
        int i = base + j;
        if (i < NN) {
            g_rowptr[i] = off0 + run;
            int bi = batch[i];
            if (i == 0) {
                for (int g = 0; g <= bi; g++) g_gptr[g] = 0;
            } else {
                int bp = batch[i - 1];
                for (int g = bp + 1; g <= bi; g++) g_gptr[g] = i;
            }
            if (i == NN - 1) {
                for (int g = bi + 1; g <= GG; g++) g_gptr[g] = NN;
            }
        }
        run += v[j];
    }
}

__global__ void k_scatter(const int* __restrict__ src, const int* __restrict__ dst) {
    int e = blockIdx.x * blockDim.x + threadIdx.x;
    if (e >= EE) return;
    int s = src[e], d = dst[e];
    int pos = g_rowptr[d] + atomicAdd(&g_cursor[d], 1);
    float ds = g_dinv[s];
    g_esrc[pos] = s;
    g_ew[pos]   = ds * g_dinv[d];
    atomicAdd(&g_rhop[d], ds);
}

// ---------------- fused per-layer-boundary kernel ----------------------------
// blocks [0,nagg): aggregation (K cols) h->g_ah
// blocks [nagg, nagg+npool): global max pool of `layer`
// blocks [nagg+npool, +convB): convert W_next (scale-folded by stats[layer])
// blocks [last 32): rank-1 offset for layer+1
#define ANPB 16
__global__ void __launch_bounds__(256)
k_aggpool(int K, int nagg, int npool, int layer,
          const float* __restrict__ gamma, const float* __restrict__ beta,
          float* __restrict__ out, const float* __restrict__ Wnext) {
    int bid = blockIdx.x;
    int tid = threadIdx.x;

    if (bid < nagg) {
        // ---- aggregation ----
        int ncg  = K >> 3;
        int cg   = (tid & (ncg - 1)) * 8;
        int sub  = tid / ncg;
        int nsub = 256 / ncg;
        int v0   = bid * ANPB;

        for (int n = sub; n < ANPB; n += nsub) {
            int v = v0 + n;
            if (v >= NN) break;
            int beg = g_rowptr[v], end = g_rowptr[v + 1];
            float di = g_dinv[v];
            float w0 = di * di;

            float acc[8];
            {
                uint4 u = *(const uint4*)(g_hf16 + (size_t)v * K + cg);
                const __half2* hp = (const __half2*)&u;
                #pragma unroll
                for (int j = 0; j < 4; j++) {
                    float2 f = __half22float2(hp[j]);
                    acc[2 * j]     = w0 * f.x;
                    acc[2 * j + 1] = w0 * f.y;
                }
            }
            int e = beg;
            for (; e + 2 <= end; e += 2) {
                float w1 = g_ew[e], w2 = g_ew[e + 1];
                int   s1 = g_esrc[e], s2 = g_esrc[e + 1];
                uint4 u1 = *(const uint4*)(g_hf16 + (size_t)s1 * K + cg);
                uint4 u2 = *(const uint4*)(g_hf16 + (size_t)s2 * K + cg);
                const __half2* h1 = (const __half2*)&u1;
                const __half2* h2 = (const __half2*)&u2;
                #pragma unroll
                for (int j = 0; j < 4; j++) {
                    float2 f1 = __half22float2(h1[j]);
                    float2 f2 = __half22float2(h2[j]);
                    acc[2 * j]     = fmaf(w1, f1.x, acc[2 * j]);
                    acc[2 * j + 1] = fmaf(w1, f1.y, acc[2 * j + 1]);
                    acc[2 * j]     = fmaf(w2, f2.x, acc[2 * j]);
                    acc[2 * j + 1] = fmaf(w2, f2.y, acc[2 * j + 1]);
                }
            }
            for (; e < end; e++) {
                float w = g_ew[e];
                int   s = g_esrc[e];
                uint4 u = *(const uint4*)(g_hf16 + (size_t)s * K + cg);
                const __half2* hp = (const __half2*)&u;
                #pragma unroll
                for (int j = 0; j < 4; j++) {
                    float2 f = __half22float2(hp[j]);
                    acc[2 * j]     = fmaf(w, f.x, acc[2 * j]);
                    acc[2 * j + 1] = fmaf(w, f.y, acc[2 * j + 1]);
                }
            }

            __align__(16) __half o[8];
            #pragma unroll
            for (int j = 0; j < 8; j++) o[j] = __float2half_rn(acc[j]);
            *(uint4*)(g_ah + (size_t)v * K + cg) = *(uint4*)o;
        }
    } else if (bid < nagg + npool) {
        // ---- pool (gamma > 0 in this dataset -> scale after max) ----
        int g = bid - nagg, c = tid;
        int beg = g_gptr[g], end = g_gptr[g + 1];
        float sc, sh;
        bn_params(layer, c, gamma, beta, sc, sh);
        float m0 = -INFINITY, m1 = -INFINITY;
        int r = beg;
        for (; r + 2 <= end; r += 2) {
            m0 = fmaxf(m0, __half2float(g_hf16[(size_t)r * RANK + c]));
            m1 = fmaxf(m1, __half2float(g_hf16[(size_t)(r + 1) * RANK + c]));
        }
        if (r < end) m0 = fmaxf(m0, __half2float(g_hf16[(size_t)r * RANK + c]));
        float m = fmaxf(m0, m1);
        out[(size_t)g * RANK + c] = (end > beg) ? fmaf(sc, m, sh) : 0.0f;
    } else {
        int convB = RANK * RANK / 256;   // 256 (K_w = RANK for layers 1,2)
        int b2 = bid - nagg - npool;
        if (b2 < convB) {
            // ---- convW for layer+1, scale-folded by stats[layer] ----
            int i = b2 * 256 + tid;
            int n = i / RANK, k = i - n * RANK;
            float sc, sh;
            bn_params(layer, k, gamma, beta, sc, sh);
            g_wh[i] = __float2half_rn(Wnext[(size_t)k * RANK + n] * sc);
        } else {
            // ---- rank-1 offset for layer+1 ----
            int b3 = b2 - convB;         // 0..31
            int n = tid;
            int kpb = RANK / 32;
            int k0 = b3 * kpb;
            float o = 0.f;
            for (int k = k0; k < k0 + kpb; k++) {
                float sc, sh;
                bn_params(layer, k, gamma, beta, sc, sh);
                o = fmaf(sh, Wnext[(size_t)k * RANK + n], o);
            }
            atomicAdd(&g_woff[(layer + 1) * RANK + n], o);
        }
    }
}

// ---------------- mma.sync fp16 GEMM (ldmatrix) + fused epilogue -------------
// CTA 128(M) x 128(N), 256 threads (8 warps 2x4), warp 64x32, K chunk 64.
#define ASTRIDE 72
#define ARB  (ASTRIDE * 2)   // 144 bytes per row
#define SA_ELEM (128 * ASTRIDE)
#define SB_ELEM (128 * ASTRIDE)
#define BUF_BYTES ((SA_ELEM + SB_ELEM) * 2)     // 36864
#define GEMM_SMEM (2 * BUF_BYTES)                // 73728

#define CP16(dst, src) do {                                                \
    uint32_t _d = (uint32_t)__cvta_generic_to_shared(dst);                 \
    asm volatile("cp.async.cg.shared.global [%0], [%1], 16;"               \
                 :: "r"(_d), "l"(src));                                    \
} while (0)

#define MMA16816(C, A, B) \
    asm volatile("mma.sync.aligned.m16n8k16.row.col.f32.f16.f16.f32 " \
        "{%0,%1,%2,%3}, {%4,%5,%6,%7}, {%8,%9}, {%0,%1,%2,%3};" \
        : "+f"((C)[0]), "+f"((C)[1]), "+f"((C)[2]), "+f"((C)[3]) \
        : "r"((A)[0]), "r"((A)[1]), "r"((A)[2]), "r"((A)[3]), \
          "r"((B)[0]), "r"((B)[1]))

#define LDSM_X4(R0, R1, R2, R3, ADDR) \
    asm volatile("ldmatrix.sync.aligned.m8n8.x4.shared.b16 {%0,%1,%2,%3}, [%4];" \
        : "=r"(R0), "=r"(R1), "=r"(R2), "=r"(R3) : "r"(ADDR))

__global__ void __launch_bounds__(256, 2)
k_gemm_mma(int K, const float* __restrict__ bias, int layer) {
    extern __shared__ __align__(16) char smem[];
    uint32_t sbase = (uint32_t)__cvta_generic_to_shared(smem);

    int tid = threadIdx.x;
    int wid = tid >> 5, lid = tid & 31;
    int m0  = blockIdx.x * 128;
    int n0  = blockIdx.y * 128;
    int wm  = (wid & 1) * 64;
    int wn  = (wid >> 1) * 32;
    int lr  = lid >> 2;
    int lc  = lid & 3;

    // ldmatrix per-lane address components
    int t8   = lid >> 3;          // tile index 0..3
    int lrow = lid & 7;
    uint32_t aOff = (uint32_t)((wm + (t8 & 1) * 8 + lrow) * ARB + (t8 >> 1) * 16);
    uint32_t bOff0 = (uint32_t)((wn + (t8 >> 1) * 8 + lrow) * ARB + (t8 & 1) * 16);
    uint32_t bOff1 = bOff0 + (uint32_t)(16 * ARB);

    float c[4][4][4];
    #pragma unroll
    for (int i = 0; i < 4; i++)
        #pragma unroll
        for (int j = 0; j < 4; j++)
            #pragma unroll
            for (int q = 0; q < 4; q++) c[i][j][q] = 0.f;

    auto load_chunk = [&](int kc, char* base) {
        __half* sA = (__half*)base;
        __half* sB = sA + SA_ELEM;
        #pragma unroll
        for (int j = 0; j < 4; j++) {
            int i = tid * 4 + j;
            int r = i >> 3, kg = i & 7;
            size_t go = (size_t)(m0 + r) * K + kc + kg * 8;
            CP16(sA + r * ASTRIDE + kg * 8, g_ah + go);
            size_t gob = (size_t)(n0 + r) * K + kc + kg * 8;
            CP16(sB + r * ASTRIDE + kg * 8, g_wh + gob);
        }
        asm volatile("cp.async.commit_group;" ::: "memory");
    };

    int nch = K >> 6;
    load_chunk(0, smem);

    for (int kc = 0; kc < nch; kc++) {
        if (kc + 1 < nch) {
            load_chunk((kc + 1) << 6, smem + ((kc + 1) & 1) * BUF_BYTES);
            asm volatile("cp.async.wait_group 1;" ::: "memory");
        } else {
            asm volatile("cp.async.wait_group 0;" ::: "memory");
        }
        __syncthreads();

        uint32_t sAaddr = sbase + (kc & 1) * BUF_BYTES;
        uint32_t sBaddr = sAaddr + SA_ELEM * 2;

        #pragma unroll
        for (int ks = 0; ks < 4; ks++) {
            uint32_t kso = (uint32_t)(ks * 32);
            uint32_t bb[4][2];
            LDSM_X4(bb[0][0], bb[0][1], bb[1][0], bb[1][1], sBaddr + bOff0 + kso);
            LDSM_X4(bb[2][0], bb[2][1], bb[3][0], bb[3][1], sBaddr + bOff1 + kso);
            #pragma unroll
            for (int fm = 0; fm < 4; fm++) {
                uint32_t aa[4];
                LDSM_X4(aa[0], aa[1], aa[2], aa[3],
                        sAaddr + aOff + (uint32_t)(fm * 16 * ARB) + kso);
                #pragma unroll
                for (int fn = 0; fn < 4; fn++)
                    MMA16816(c[fm][fn], aa, bb[fn]);
            }
        }
        __syncthreads();
    }

    // ---- fused epilogue: y = acc + rho*woff + bias; h = tanh(y) ----
    const float* woff = g_woff + layer * RANK;
    float woffv[8], biasv[8];
    #pragma unroll
    for (int fn = 0; fn < 4; fn++) {
        int col = n0 + wn + fn * 8 + lc * 2;
        woffv[fn * 2]     = woff[col];
        woffv[fn * 2 + 1] = woff[col + 1];
        biasv[fn * 2]     = bias[col];
        biasv[fn * 2 + 1] = bias[col + 1];
    }

    float ts[8], tq[8];
    #pragma unroll
    for (int j = 0; j < 8; j++) { ts[j] = 0.f; tq[j] = 0.f; }

    #pragma unroll
    for (int fm = 0; fm < 4; fm++) {
        int r0 = m0 + wm + fm * 16 + lr;
        int r1 = r0 + 8;
        float rho0 = 0.f, rho1 = 0.f;
        if (r0 < NN) { float d = g_dinv[r0]; rho0 = d * (g_rhop[r0] + d); }
        if (r1 < NN) { float d = g_dinv[r1]; rho1 = d * (g_rhop[r1] + d); }
        #pragma unroll
        for (int fn = 0; fn < 4; fn++) {
            int col = n0 + wn + fn * 8 + lc * 2;
            float w0v = woffv[fn * 2], w1v = woffv[fn * 2 + 1];
            float b0v = biasv[fn * 2], b1v = biasv[fn * 2 + 1];
            if (r0 < NN) {
                float h00 = tanhf(c[fm][fn][0] + rho0 * w0v + b0v);
                float h01 = tanhf(c[fm][fn][1] + rho0 * w1v + b1v);
                *(__half2*)(g_hf16 + (size_t)r0 * RANK + col) = __floats2half2_rn(h00, h01);
                ts[fn * 2] += h00;     tq[fn * 2]     = fmaf(h00, h00, tq[fn * 2]);
                ts[fn * 2 + 1] += h01; tq[fn * 2 + 1] = fmaf(h01, h01, tq[fn * 2 + 1]);
            }
            if (r1 < NN) {
                float h10 = tanhf(c[fm][fn][2] + rho1 * w0v + b0v);
                float h11 = tanhf(c[fm][fn][3] + rho1 * w1v + b1v);
                *(__half2*)(g_hf16 + (size_t)r1 * RANK + col) = __floats2half2_rn(h10, h11);
                ts[fn * 2] += h10;     tq[fn * 2]     = fmaf(h10, h10, tq[fn * 2]);
                ts[fn * 2 + 1] += h11; tq[fn * 2 + 1] = fmaf(h11, h11, tq[fn * 2 + 1]);
            }
        }
    }

    #pragma unroll
    for (int off = 4; off < 32; off <<= 1) {
        #pragma unroll
        for (int j = 0; j < 8; j++) {
            ts[j] += __shfl_xor_sync(0xffffffff, ts[j], off);
            tq[j] += __shfl_xor_sync(0xffffffff, tq[j], off);
        }
    }

    float* red = (float*)smem;   // [0:128) sum, [128:256) sq
    __syncthreads();
    if (tid < 128) { red[tid] = 0.f; red[128 + tid] = 0.f; }
    __syncthreads();
    if (lr == 0) {
        #pragma unroll
        for (int fn = 0; fn < 4; fn++) {
            int lcol = wn + fn * 8 + lc * 2;
            atomicAdd(&red[lcol],           ts[fn * 2]);
            atomicAdd(&red[lcol + 1],       ts[fn * 2 + 1]);
            atomicAdd(&red[128 + lcol],     tq[fn * 2]);
            atomicAdd(&red[128 + lcol + 1], tq[fn * 2 + 1]);
        }
    }
    __syncthreads();
    if (tid < 128) {
        atomicAdd(&g_sum[layer * RANK + n0 + tid],   red[tid]);
        atomicAdd(&g_sumsq[layer * RANK + n0 + tid], red[128 + tid]);
    }
}

// ---------------- launch ----------------------------------------------------
extern "C" void kernel_launch(void* const* d_in, const int* in_sizes, int n_in,
                              void* d_out, int out_size) {
    const float* x     = (const float*)d_in[0];
    const int*   ei    = (const int*)  d_in[1];   // [2, E] int32
    const int*   batch = (const int*)  d_in[2];
    const float* W[3]     = { (const float*)d_in[3],  (const float*)d_in[7],  (const float*)d_in[11] };
    const float* b[3]     = { (const float*)d_in[4],  (const float*)d_in[8],  (const float*)d_in[12] };
    const float* gamma[3] = { (const float*)d_in[5],  (const float*)d_in[9],  (const float*)d_in[13] };
    const float* beta[3]  = { (const float*)d_in[6],  (const float*)d_in[10], (const float*)d_in[14] };
    const int* src = ei;
    const int* dst = ei + EE;
    float* out = (float*)d_out;

    cudaFuncSetAttribute(k_gemm_mma, cudaFuncAttributeMaxDynamicSharedMemorySize, GEMM_SMEM);

    k_init     <<<(NN + 255) / 256, 256>>>();
    k_histconv <<<HISTB + CONVW0B + CONVXB, 256>>>(dst, W[0], x);
    k_dinvscan1<<<98, 256>>>();
    k_scan3gptr<<<98, 256>>>(batch);
    k_scatter  <<<(EE + 255) / 256, 256>>>(src, dst);

    dim3 gemm_grid((NN + 127) / 128, 2);   // 782 x 2
    int ablocks = (NN + ANPB - 1) / ANPB;  // 6250
    int convB   = RANK * RANK / 256 + 32;  // convW + offset blocks

    // layer 0: agg(x) -> gemm
    k_aggpool<<<ablocks, 256>>>(DIN, ablocks, 0, 0, gamma[0], beta[0], out, W[1]);
    k_gemm_mma<<<gemm_grid, 256, GEMM_SMEM>>>(DIN, b[0], 0);

    // layer boundary 0->1: agg(h0) + pool0 + convW1 + woff1
    k_aggpool<<<ablocks + GG + convB, 256>>>(RANK, ablocks, GG, 0,
                                             gamma[0], beta[0], out, W[1]);
    k_gemm_mma<<<gemm_grid, 256, GEMM_SMEM>>>(RANK, b[1], 1);

    // layer boundary 1->2
    k_aggpool<<<ablocks + GG + convB, 256>>>(RANK, ablocks, GG, 1,
                                             gamma[1], beta[1],
                                             out + (size_t)GG * RANK, W[2]);
    k_gemm_mma<<<gemm_grid, 256, GEMM_SMEM>>>(RANK, b[2], 2);

    // final pool (layer 2)
    k_aggpool<<<GG, 256>>>(RANK, 0, GG, 2, gamma[2], beta[2],
                           out + (size_t)2 * GG * RANK, W[2]);
}